// round 11
// baseline (speedup 1.0000x reference)
#include <cuda_runtime.h>
#include <cuda_bf16.h>
#include <cuda_fp16.h>
#include <math.h>
#include <stdint.h>

// ---------------------------------------------------------------------------
// VisionModel: S=1280, D=1280, H=16, HD=80, DEPTH=4. Output (320,1536) fp32.
// GEMMs: fp16 mma, BM=BN=128 BK=32, 4 warps x 64x64 (smem-traffic-minimized).
// FA2 attention w/ fused RoPE. LN fp32.
// ---------------------------------------------------------------------------

#define S_TOK 1280
#define DMODEL 1280
#define NHEAD 16
#define HDIM 80
#define DEPTH 4

__device__ float g_x[S_TOK * DMODEL];
__device__ float g_ln[S_TOK * DMODEL];
__device__ float g_qkv[S_TOK * 3 * DMODEL];   // also m2 split-K partials
__device__ float g_att[S_TOK * DMODEL];
__device__ float g_big[S_TOK * 4 * DMODEL];
__device__ float g_part[4 * DMODEL * S_TOK];  // split-K partials
__device__ float g_rcos[S_TOK * 40];
__device__ float g_rsin[S_TOK * 40];

// ===========================================================================

__device__ __forceinline__ uint32_t pack_f16(float lo, float hi) {
    uint32_t r;
    asm("cvt.rn.f16x2.f32 %0, %1, %2;" : "=r"(r) : "f"(hi), "f"(lo));
    return r;
}

__device__ __forceinline__ void mma_f16(float* c,
    uint32_t a0, uint32_t a1, uint32_t a2, uint32_t a3,
    uint32_t b0, uint32_t b1)
{
    asm volatile(
        "mma.sync.aligned.m16n8k16.row.col.f32.f16.f16.f32 "
        "{%0,%1,%2,%3},{%4,%5,%6,%7},{%8,%9},{%0,%1,%2,%3};"
        : "+f"(c[0]), "+f"(c[1]), "+f"(c[2]), "+f"(c[3])
        : "r"(a0), "r"(a1), "r"(a2), "r"(a3), "r"(b0), "r"(b1));
}

template <int OP>
__device__ __forceinline__ float ep_op(float t, float r) {
    if (OP == 0 || OP == 4) return t;
    else if (OP == 1) return t + r;
    else if (OP == 2) return t / (1.f + __expf(-1.702f * t));
    else return 0.5f * t * (1.f + erff(t * 0.7071067811865475f));
}

__device__ __forceinline__ int swz(int r) { return ((r ^ (r >> 2)) & 3) << 1; }

// ===========================================================================
// fp16 GEMM: C = A@B^T + bias. OP 0 none/1 resid/2 SiLU/3 GELU/4 splitK part.
// 128 threads = 4 warps, warp tile 64x64. BK=32 = 2 x BK16 sub-tiles.
// Producer: thread tid owns row tid of A and B, STS.64 (conflict-free by
// 16-lane phasing + swizzle distinct on r,r+4,r+8,r+12).
// ===========================================================================
template <int OP>
__global__ __launch_bounds__(128, 2) void gemm_f16(
    const float* __restrict__ A, int lda,
    const float* __restrict__ B, int ldb,
    const float* __restrict__ bias, const float* __restrict__ resid,
    float* __restrict__ C, int M, int N, int K)
{
    // [buf][k16-subtile][128 rows x 8 pair-cols]
    __shared__ uint32_t As[2][2][128 * 8];
    __shared__ uint32_t Bs[2][2][128 * 8];

    if (OP == 4) {
        const size_t zo = (size_t)blockIdx.z * K;
        A += zo; B += zo;
        C += (size_t)blockIdx.z * (size_t)M * N;
    }

    const int tid  = threadIdx.x;
    const int warp = tid >> 5;
    const int lane = tid & 31;
    const int g = lane >> 2;
    const int t = lane & 3;

    const int m0 = blockIdx.y * 128;
    const int n0 = blockIdx.x * 128;
    const int warp_m = (warp & 1) * 64;
    const int warp_n = (warp >> 1) * 64;

    // producer: one thread per row (A row tid, B row tid), all 32 k
    const int prow = tid;
    const bool arow_ok = (m0 + prow) < M;
    const float* Ag = A + (size_t)(m0 + prow) * lda;
    const float* Bg = B + (size_t)(n0 + prow) * ldb;
    const int psw = swz(prow);

    float acc[4][8][4];
#pragma unroll
    for (int am = 0; am < 4; am++)
#pragma unroll
        for (int bn = 0; bn < 8; bn++)
#pragma unroll
            for (int i = 0; i < 4; i++) acc[am][bn][i] = 0.f;

    const float4 z4 = make_float4(0.f, 0.f, 0.f, 0.f);
    uint32_t pka[16], pkb[16];  // packed pairs: p = s*8 + k2

#define LOAD_PACK32(k0)                                                        \
    {                                                                          \
        _Pragma("unroll")                                                      \
        for (int j4 = 0; j4 < 8; j4++) {                                       \
            float4 va = (arow_ok && (k0) + j4 * 4 < K)                         \
                            ? *(const float4*)(Ag + (k0) + j4 * 4) : z4;       \
            float4 vb = ((k0) + j4 * 4 < K)                                    \
                            ? *(const float4*)(Bg + (k0) + j4 * 4) : z4;       \
            pka[2 * j4]     = pack_f16(va.x, va.y);                            \
            pka[2 * j4 + 1] = pack_f16(va.z, va.w);                            \
            pkb[2 * j4]     = pack_f16(vb.x, vb.y);                            \
            pkb[2 * j4 + 1] = pack_f16(vb.z, vb.w);                            \
        }                                                                      \
    }

    // store pairs {k2=j, k2=j+4} as uint2 at pair-col (2j)^psw of sub-tile s
#define STORE_PACK32(buf_)                                                     \
    {                                                                          \
        _Pragma("unroll")                                                      \
        for (int s_ = 0; s_ < 2; s_++) {                                       \
            _Pragma("unroll")                                                  \
            for (int j = 0; j < 4; j++) {                                      \
                const int idx = prow * 8 + ((2 * j) ^ psw);                    \
                *(uint2*)&As[buf_][s_][idx] =                                  \
                    make_uint2(pka[8 * s_ + j], pka[8 * s_ + j + 4]);          \
                *(uint2*)&Bs[buf_][s_][idx] =                                  \
                    make_uint2(pkb[8 * s_ + j], pkb[8 * s_ + j + 4]);          \
            }                                                                  \
        }                                                                      \
    }

    LOAD_PACK32(0);
    STORE_PACK32(0);
    __syncthreads();

    int aoff[4][2], boff[8];
#pragma unroll
    for (int am = 0; am < 4; am++) {
        const int rl = warp_m + am * 16 + g;
        const int rh = rl + 8;
        aoff[am][0] = rl * 8 + ((2 * t) ^ swz(rl));
        aoff[am][1] = rh * 8 + ((2 * t) ^ swz(rh));
    }
#pragma unroll
    for (int bn = 0; bn < 8; bn++) {
        const int rn = warp_n + bn * 8 + g;
        boff[bn] = rn * 8 + ((2 * t) ^ swz(rn));
    }

    const int nstages = (K + 31) >> 5;
    int buf = 0;

    for (int s = 0; s < nstages; s++) {
        const bool has_next = (s + 1 < nstages);
        if (has_next) LOAD_PACK32((s + 1) << 5);

#pragma unroll
        for (int ks2 = 0; ks2 < 2; ks2++) {
            const uint32_t* Ab = As[buf][ks2];
            const uint32_t* Bb = Bs[buf][ks2];
            uint2 afl[4], afh[4];
#pragma unroll
            for (int am = 0; am < 4; am++) {
                afl[am] = *(const uint2*)&Ab[aoff[am][0]];
                afh[am] = *(const uint2*)&Ab[aoff[am][1]];
            }
            uint2 bf[8];
#pragma unroll
            for (int bn = 0; bn < 8; bn++) bf[bn] = *(const uint2*)&Bb[boff[bn]];

#pragma unroll
            for (int am = 0; am < 4; am++)
#pragma unroll
                for (int bn = 0; bn < 8; bn++)
                    mma_f16(acc[am][bn],
                            afl[am].x, afh[am].x, afl[am].y, afh[am].y,
                            bf[bn].x, bf[bn].y);
        }

        if (has_next) STORE_PACK32(buf ^ 1);
        __syncthreads();
        buf ^= 1;
    }
#undef LOAD_PACK32
#undef STORE_PACK32

#pragma unroll
    for (int am = 0; am < 4; am++) {
        const int r0 = m0 + warp_m + am * 16 + g;
        const int r1 = r0 + 8;
#pragma unroll
        for (int bn = 0; bn < 8; bn++) {
            const int col = n0 + warp_n + bn * 8 + t * 2;
            const float2 bb = bias ? *(const float2*)&bias[col]
                                   : make_float2(0.f, 0.f);
            const float* cc = acc[am][bn];
            if (r0 < M) {
                float rx = 0.f, ry = 0.f;
                if (OP == 1) { const float2 rr = *(const float2*)&resid[(size_t)r0 * N + col]; rx = rr.x; ry = rr.y; }
                float2 o; o.x = ep_op<OP>(cc[0] + bb.x, rx); o.y = ep_op<OP>(cc[1] + bb.y, ry);
                *(float2*)&C[(size_t)r0 * N + col] = o;
            }
            if (r1 < M) {
                float rx = 0.f, ry = 0.f;
                if (OP == 1) { const float2 rr = *(const float2*)&resid[(size_t)r1 * N + col]; rx = rr.x; ry = rr.y; }
                float2 o; o.x = ep_op<OP>(cc[2] + bb.x, rx); o.y = ep_op<OP>(cc[3] + bb.y, ry);
                *(float2*)&C[(size_t)r1 * N + col] = o;
            }
        }
    }
}

// ===========================================================================
// split-K reduce: MODE 0: dst = sum+bias; 1: dst += sum+bias; 3: GELU(sum+bias)
// ===========================================================================
template <int NP, int MODE>
__global__ void reduce_k(const float* __restrict__ part,
                         const float* __restrict__ bias,
                         float* __restrict__ dst, int total, int ncols)
{
    const int i = blockIdx.x * 256 + threadIdx.x;
    if (i >= total) return;
    float s = bias[i % ncols];
#pragma unroll
    for (int c = 0; c < NP; c++) s += part[(size_t)c * total + i];
    if (MODE == 0) dst[i] = s;
    else if (MODE == 1) dst[i] += s;
    else dst[i] = 0.5f * s * (1.f + erff(s * 0.7071067811865475f));
}

// ---------------------------------------------------------------------------
// RoPE cos/sin tables
// ---------------------------------------------------------------------------
__global__ void rope_table(const float* __restrict__ rotary,
                           float* __restrict__ rcos, float* __restrict__ rsin)
{
    const int i = blockIdx.x * 256 + threadIdx.x;
    if (i >= S_TOK * 40) return;
    float c, s;
    sincosf(rotary[i], &s, &c);
    rcos[i] = c;
    rsin[i] = s;
}

// ---------------------------------------------------------------------------
// LayerNorm
// ---------------------------------------------------------------------------
__global__ __launch_bounds__(256) void ln_kernel(
    const float* __restrict__ x, const float* __restrict__ w,
    const float* __restrict__ b, float* __restrict__ y)
{
    const int row = blockIdx.x;
    const int tid = threadIdx.x;
    const float* xr = x + (size_t)row * DMODEL;

    float s = 0.f, sq = 0.f;
#pragma unroll
    for (int i = 0; i < DMODEL / 256; i++) {
        float v = xr[tid + i * 256];
        s += v; sq += v * v;
    }
#pragma unroll
    for (int o = 16; o > 0; o >>= 1) {
        s  += __shfl_xor_sync(0xffffffffu, s, o);
        sq += __shfl_xor_sync(0xffffffffu, sq, o);
    }
    __shared__ float ws[8], wsq[8];
    if ((tid & 31) == 0) { ws[tid >> 5] = s; wsq[tid >> 5] = sq; }
    __syncthreads();
    __shared__ float s_mu, s_rstd;
    if (tid == 0) {
        float ts = 0.f, tsq = 0.f;
        for (int i = 0; i < 8; i++) { ts += ws[i]; tsq += wsq[i]; }
        float mu = ts / DMODEL;
        float var = tsq / DMODEL - mu * mu;
        s_mu = mu;
        s_rstd = rsqrtf(var + 1e-6f);
    }
    __syncthreads();
    float mu = s_mu, rstd = s_rstd;
    float* yr = y + (size_t)row * DMODEL;
#pragma unroll
    for (int i = 0; i < DMODEL / 256; i++) {
        int c = tid + i * 256;
        yr[c] = (xr[c] - mu) * rstd * w[c] + b[c];
    }
}

// ===========================================================================
// Attention: FA2-style fp16 mma (fp32 accum), 128 thr = 4 warps, fused RoPE.
// ===========================================================================
#define AT_STRIDE 88

__device__ __forceinline__ void ldsm4(uint32_t* r, uint32_t addr) {
    asm volatile("ldmatrix.sync.aligned.m8n8.x4.shared.b16 {%0,%1,%2,%3}, [%4];"
                 : "=r"(r[0]), "=r"(r[1]), "=r"(r[2]), "=r"(r[3]) : "r"(addr));
}
__device__ __forceinline__ void ldsm4t(uint32_t* r, uint32_t addr) {
    asm volatile("ldmatrix.sync.aligned.m8n8.x4.trans.shared.b16 {%0,%1,%2,%3}, [%4];"
                 : "=r"(r[0]), "=r"(r[1]), "=r"(r[2]), "=r"(r[3]) : "r"(addr));
}

__device__ __forceinline__ void load_rope_half(
    const float* __restrict__ src, const float* __restrict__ srco,
    const float* __restrict__ tc, const float* __restrict__ ts,
    float sgn, float scale, __half* dst)
{
#pragma unroll
    for (int j = 0; j < 10; j++) {
        float4 v = *(const float4*)(src + j * 4);
        float4 w = *(const float4*)(srco + j * 4);
        float4 c = *(const float4*)(tc + j * 4);
        float4 s = *(const float4*)(ts + j * 4);
        float o0 = (v.x * c.x + sgn * w.x * s.x) * scale;
        float o1 = (v.y * c.y + sgn * w.y * s.y) * scale;
        float o2 = (v.z * c.z + sgn * w.z * s.z) * scale;
        float o3 = (v.w * c.w + sgn * w.w * s.w) * scale;
        *(uint2*)(dst + j * 4) = make_uint2(pack_f16(o0, o1), pack_f16(o2, o3));
    }
}

__global__ __launch_bounds__(128) void attn_f16(
    const float* __restrict__ qkv, const int* __restrict__ seg,
    const float* __restrict__ rcos, const float* __restrict__ rsin,
    float* __restrict__ out)
{
    __shared__ __half Qs[64 * AT_STRIDE];
    __shared__ __half Ks[64 * AT_STRIDE];
    __shared__ __half Vs[64 * AT_STRIDE];

    const int head = blockIdx.x;
    const int q0   = blockIdx.y * 64;
    const int tid  = threadIdx.x;
    const int w    = tid >> 5;
    const int lane = tid & 31;
    const int g    = lane >> 2;
    const int t    = lane & 3;

    const float scale = 0.11180339887498949f;

    uint32_t qb, kb, vb;
    asm("{ .reg .u64 u; cvta.to.shared.u64 u, %1; cvt.u32.u64 %0, u; }" : "=r"(qb) : "l"(Qs));
    asm("{ .reg .u64 u; cvta.to.shared.u64 u, %1; cvt.u32.u64 %0, u; }" : "=r"(kb) : "l"(Ks));
    asm("{ .reg .u64 u; cvta.to.shared.u64 u, %1; cvt.u32.u64 %0, u; }" : "=r"(vb) : "l"(Vs));

    const int lrow = tid >> 1;
    const int lh   = tid & 1;
    const float sgn = lh ? 1.f : -1.f;

    {
        const float* base = qkv + (size_t)(q0 + lrow) * (3 * DMODEL) + head * HDIM;
        load_rope_half(base + lh * 40, base + (1 - lh) * 40,
                       rcos + (q0 + lrow) * 40, rsin + (q0 + lrow) * 40,
                       sgn, scale, Qs + lrow * AT_STRIDE + lh * 40);
    }

    float m[2] = {-1e30f, -1e30f};
    float l[2] = {0.f, 0.f};
    float oacc[10][4];
#pragma unroll
    for (int j = 0; j < 10; j++)
#pragma unroll
        for (int i = 0; i < 4; i++) oacc[j][i] = 0.f;

    const int myseg = seg[q0];

    const uint32_t lrow16 = (uint32_t)(lane & 15);
    const uint32_t lhi16  = (uint32_t)(lane >> 4) * 16;
    const uint32_t q_addr0 = qb + (w * 16 + lrow16) * (AT_STRIDE * 2) + lhi16;

    __syncthreads();

    for (int c0 = 0; c0 < S_TOK; c0 += 64) {
        if (seg[c0] != myseg) continue;

        {
            const float* baseK = qkv + (size_t)(c0 + lrow) * (3 * DMODEL) + DMODEL + head * HDIM;
            load_rope_half(baseK + lh * 40, baseK + (1 - lh) * 40,
                           rcos + (c0 + lrow) * 40, rsin + (c0 + lrow) * 40,
                           sgn, 1.f, Ks + lrow * AT_STRIDE + lh * 40);
            const float* srcV = baseK + DMODEL + lh * 40;
            __half* dV = Vs + lrow * AT_STRIDE + lh * 40;
#pragma unroll
            for (int j = 0; j < 10; j++) {
                float4 u = *(const float4*)(srcV + j * 4);
                *(uint2*)(dV + j * 4) = make_uint2(pack_f16(u.x, u.y), pack_f16(u.z, u.w));
            }
        }
        __syncthreads();

        float sacc[8][4];
#pragma unroll
        for (int j = 0; j < 8; j++)
#pragma unroll
            for (int i = 0; i < 4; i++) sacc[j][i] = 0.f;

#pragma unroll
        for (int ks = 0; ks < 5; ks++) {
            uint32_t aq[4];
            ldsm4(aq, q_addr0 + ks * 32);
#pragma unroll
            for (int nb = 0; nb < 4; nb++) {
                uint32_t kr[4];
                ldsm4(kr, kb + (nb * 16 + lrow16) * (AT_STRIDE * 2) + lhi16 + ks * 32);
                mma_f16(sacc[2 * nb],     aq[0], aq[1], aq[2], aq[3], kr[0], kr[2]);
                mma_f16(sacc[2 * nb + 1], aq[0], aq[1], aq[2], aq[3], kr[1], kr[3]);
            }
        }

        float cs[2];
#pragma unroll
        for (int i = 0; i < 2; i++) {
            float cm = -1e30f;
#pragma unroll
            for (int j = 0; j < 8; j++) {
                cm = fmaxf(cm, sacc[j][2 * i]);
                cm = fmaxf(cm, sacc[j][2 * i + 1]);
            }
            cm = fmaxf(cm, __shfl_xor_sync(0xffffffffu, cm, 1));
            cm = fmaxf(cm, __shfl_xor_sync(0xffffffffu, cm, 2));
            const float nm = fmaxf(m[i], cm);
            cs[i] = __expf(m[i] - nm);
            m[i] = nm;
            float ps = 0.f;
#pragma unroll
            for (int j = 0; j < 8; j++) {
                float p0 = __expf(sacc[j][2 * i] - nm);
                float p1 = __expf(sacc[j][2 * i + 1] - nm);
                sacc[j][2 * i] = p0; sacc[j][2 * i + 1] = p1;
                ps += p0 + p1;
            }
            ps += __shfl_xor_sync(0xffffffffu, ps, 1);
            ps += __shfl_xor_sync(0xffffffffu, ps, 2);
            l[i] = l[i] * cs[i] + ps;
        }
#pragma unroll
        for (int j = 0; j < 10; j++) {
            oacc[j][0] *= cs[0]; oacc[j][1] *= cs[0];
            oacc[j][2] *= cs[1]; oacc[j][3] *= cs[1];
        }

#pragma unroll
        for (int ks = 0; ks < 4; ks++) {
            uint32_t pp[4];
            pp[0] = pack_f16(sacc[2 * ks][0],     sacc[2 * ks][1]);
            pp[1] = pack_f16(sacc[2 * ks][2],     sacc[2 * ks][3]);
            pp[2] = pack_f16(sacc[2 * ks + 1][0], sacc[2 * ks + 1][1]);
            pp[3] = pack_f16(sacc[2 * ks + 1][2], sacc[2 * ks + 1][3]);
#pragma unroll
            for (int db = 0; db < 5; db++) {
                uint32_t vr[4];
                ldsm4t(vr, vb + (ks * 16 + lrow16) * (AT_STRIDE * 2) + db * 32 + lhi16);
                mma_f16(oacc[2 * db],     pp[0], pp[1], pp[2], pp[3], vr[0], vr[1]);
                mma_f16(oacc[2 * db + 1], pp[0], pp[1], pp[2], pp[3], vr[2], vr[3]);
            }
        }
        __syncthreads();
    }

    const float inv0 = 1.f / l[0];
    const float inv1 = 1.f / l[1];
    const int r0 = q0 + w * 16 + g;
#pragma unroll
    for (int j = 0; j < 10; j++) {
        const int d = head * HDIM + j * 8 + t * 2;
        *(float2*)&out[(size_t)r0 * DMODEL + d] =
            make_float2(oacc[j][0] * inv0, oacc[j][1] * inv0);
        *(float2*)&out[(size_t)(r0 + 8) * DMODEL + d] =
            make_float2(oacc[j][2] * inv1, oacc[j][3] * inv1);
    }
}

// ---------------------------------------------------------------------------
// Host side
// ---------------------------------------------------------------------------
static inline void run_gemm(int op, const float* A, int lda, const float* B, int ldb,
                            const float* bias, const float* resid,
                            float* C, int M, int N, int K)
{
    dim3 grid(N / 128, (M + 127) / 128);
    switch (op) {
        case 0: gemm_f16<0><<<grid, 128>>>(A, lda, B, ldb, bias, resid, C, M, N, K); break;
        case 1: gemm_f16<1><<<grid, 128>>>(A, lda, B, ldb, bias, resid, C, M, N, K); break;
        case 2: gemm_f16<2><<<grid, 128>>>(A, lda, B, ldb, bias, resid, C, M, N, K); break;
        case 3: gemm_f16<3><<<grid, 128>>>(A, lda, B, ldb, bias, resid, C, M, N, K); break;
    }
}

static inline void run_gemm_splitk(int parts, const float* A, int ld,
                                   const float* B, float* part_buf,
                                   int M, int N, int Kfull)
{
    dim3 grid(N / 128, (M + 127) / 128, parts);
    gemm_f16<4><<<grid, 128>>>(A, ld, B, ld, nullptr, nullptr,
                               part_buf, M, N, Kfull / parts);
}

extern "C" void kernel_launch(void* const* d_in, const int* in_sizes, int n_in,
                              void* d_out, int out_size)
{
    const float* pixels  = (const float*)d_in[0];
    const float* rotary  = (const float*)d_in[1];
    const int*   seg_ids = (const int*)d_in[2];
    const float* proj_w  = (const float*)d_in[3];
    const float* ln1_w   = (const float*)d_in[4];
    const float* ln1_b   = (const float*)d_in[5];
    const float* qkv_w   = (const float*)d_in[6];
    const float* qkv_b   = (const float*)d_in[7];
    const float* po_w    = (const float*)d_in[8];
    const float* po_b    = (const float*)d_in[9];
    const float* ln2_w   = (const float*)d_in[10];
    const float* ln2_b   = (const float*)d_in[11];
    const float* fc1_w   = (const float*)d_in[12];
    const float* fc1_b   = (const float*)d_in[13];
    const float* fc2_w   = (const float*)d_in[14];
    const float* fc2_b   = (const float*)d_in[15];
    const float* mln_w   = (const float*)d_in[16];
    const float* mln_b   = (const float*)d_in[17];
    const float* m1_w    = (const float*)d_in[18];
    const float* m1_b    = (const float*)d_in[19];
    const float* m2_w    = (const float*)d_in[20];
    const float* m2_b    = (const float*)d_in[21];
    float* out = (float*)d_out;

    float *x, *ln, *qkv, *att, *big, *part, *rcos, *rsin;
    cudaGetSymbolAddress((void**)&x,    g_x);
    cudaGetSymbolAddress((void**)&ln,   g_ln);
    cudaGetSymbolAddress((void**)&qkv,  g_qkv);
    cudaGetSymbolAddress((void**)&att,  g_att);
    cudaGetSymbolAddress((void**)&big,  g_big);
    cudaGetSymbolAddress((void**)&part, g_part);
    cudaGetSymbolAddress((void**)&rcos, g_rcos);
    cudaGetSymbolAddress((void**)&rsin, g_rsin);

    rope_table<<<(S_TOK * 40 + 255) / 256, 256>>>(rotary, rcos, rsin);

    // patch projection: x = pixels @ proj_w^T (K=1176, no bias)
    run_gemm(0, pixels, 1176, proj_w, 1176, nullptr, nullptr, x, S_TOK, DMODEL, 1176);

    for (int l = 0; l < DEPTH; l++) {
        ln_kernel<<<S_TOK, 256>>>(x, ln1_w + l * DMODEL, ln1_b + l * DMODEL, ln);
        run_gemm(0, ln, DMODEL, qkv_w + (size_t)l * 3 * DMODEL * DMODEL, DMODEL,
                 qkv_b + (size_t)l * 3 * DMODEL, nullptr, qkv,
                 S_TOK, 3 * DMODEL, DMODEL);
        {
            dim3 grid(NHEAD, S_TOK / 64);
            attn_f16<<<grid, 128>>>(qkv, seg_ids, rcos, rsin, att);
        }
        run_gemm_splitk(2, att, DMODEL, po_w + (size_t)l * DMODEL * DMODEL, part,
                        S_TOK, DMODEL, DMODEL);
        reduce_k<2, 1><<<(S_TOK * DMODEL + 255) / 256, 256>>>(
            part, po_b + (size_t)l * DMODEL, x, S_TOK * DMODEL, DMODEL);

        ln_kernel<<<S_TOK, 256>>>(x, ln2_w + l * DMODEL, ln2_b + l * DMODEL, ln);
        run_gemm(2, ln, DMODEL, fc1_w + (size_t)l * 4 * DMODEL * DMODEL, DMODEL,
                 fc1_b + (size_t)l * 4 * DMODEL, nullptr, big,
                 S_TOK, 4 * DMODEL, DMODEL);
        run_gemm_splitk(4, big, 4 * DMODEL,
                        fc2_w + (size_t)l * DMODEL * 4 * DMODEL, part,
                        S_TOK, DMODEL, 4 * DMODEL);
        reduce_k<4, 1><<<(S_TOK * DMODEL + 255) / 256, 256>>>(
            part, fc2_b + (size_t)l * DMODEL, x, S_TOK * DMODEL, DMODEL);
    }

    ln_kernel<<<S_TOK, 256>>>(x, mln_w, mln_b, ln);
    run_gemm_splitk(2, ln, 4 * DMODEL, m1_w, part, S_TOK / 4, 4 * DMODEL, 4 * DMODEL);
    reduce_k<2, 3><<<(320 * 4 * DMODEL + 255) / 256, 256>>>(
        part, m1_b, big, 320 * 4 * DMODEL, 4 * DMODEL);
    run_gemm_splitk(4, big, 4 * DMODEL, m2_w, qkv, 320, 1536, 4 * DMODEL);
    reduce_k<4, 0><<<(320 * 1536 + 255) / 256, 256>>>(
        qkv, m2_b, out, 320 * 1536, 1536);
}

// round 12
// speedup vs baseline: 1.4073x; 1.4073x over previous
#include <cuda_runtime.h>
#include <cuda_bf16.h>
#include <cuda_fp16.h>
#include <math.h>
#include <stdint.h>

// ---------------------------------------------------------------------------
// VisionModel: S=1280, D=1280, H=16, HD=80, DEPTH=4. Output (320,1536) fp32.
// All GEMM operands staged fp16. GEMM: 128x256 block, 8 warps x 64x64, BK=32.
// FA2 attention (fp16 in/out) w/ fused RoPE. LN fp32->fp16. Residual fp32.
// ---------------------------------------------------------------------------

#define S_TOK 1280
#define DMODEL 1280
#define NHEAD 16
#define HDIM 80
#define DEPTH 4
#define KPAD 1184   // pixels/proj K padded 1176 -> 1184 (mult of 32)

// fp16 weight/activation staging buffers
__device__ __half g_pix_h [S_TOK * KPAD];
__device__ __half g_projw_h[DMODEL * KPAD];
__device__ __half g_qkvw_h[DEPTH * 3 * DMODEL * DMODEL];
__device__ __half g_pow_h [DEPTH * DMODEL * DMODEL];
__device__ __half g_fc1w_h[DEPTH * 4 * DMODEL * DMODEL];
__device__ __half g_fc2w_h[DEPTH * DMODEL * 4 * DMODEL];
__device__ __half g_m1w_h [4 * DMODEL * 4 * DMODEL];
__device__ __half g_m2w_h [1536 * 4 * DMODEL];
__device__ __half g_ln_h  [S_TOK * DMODEL];
__device__ __half g_qkv_h [S_TOK * 3 * DMODEL];
__device__ __half g_att_h [S_TOK * DMODEL];
__device__ __half g_big_h [S_TOK * 4 * DMODEL];
// fp32
__device__ float g_x[S_TOK * DMODEL];
__device__ float g_part[4 * DMODEL * S_TOK];  // split-K partials (all users fit)
__device__ float g_rcos[S_TOK * 40];
__device__ float g_rsin[S_TOK * 40];

// ===========================================================================

__device__ __forceinline__ uint32_t pack_f16(float lo, float hi) {
    uint32_t r;
    asm("cvt.rn.f16x2.f32 %0, %1, %2;" : "=r"(r) : "f"(hi), "f"(lo));
    return r;
}

__device__ __forceinline__ void mma_f16(float* c,
    uint32_t a0, uint32_t a1, uint32_t a2, uint32_t a3,
    uint32_t b0, uint32_t b1)
{
    asm volatile(
        "mma.sync.aligned.m16n8k16.row.col.f32.f16.f16.f32 "
        "{%0,%1,%2,%3},{%4,%5,%6,%7},{%8,%9},{%0,%1,%2,%3};"
        : "+f"(c[0]), "+f"(c[1]), "+f"(c[2]), "+f"(c[3])
        : "r"(a0), "r"(a1), "r"(a2), "r"(a3), "r"(b0), "r"(b1));
}

__device__ __forceinline__ int swz(int r) { return ((r ^ (r >> 2)) & 3) << 1; }

// ===========================================================================
// fp16 GEMM: C = A@B^T (+bias). OP 0: fp32 out; 4: split-K fp32 partial;
// 5: fp16 out (+bias); 6: fp16 SiLU out (+bias).
// Block 128x256, 256 thr = 8 warps (2x4), warp 64x64, BK=32 (2x k16 subtiles).
// smem (dynamic, 49,280B):
//   A(buf,sub) = sm + buf*2064 + sub*1040   (16-u32 pad between subs)
//   B(buf,sub) = sm + 4128 + buf*4096 + sub*2048
// Requires N % 256 == 0, K % 32 == 0. M ragged OK (A rows guarded).
// ===========================================================================
#define GEMM_SMEM_BYTES ((4128 + 8192) * 4)

template <int OP>
__global__ __launch_bounds__(256) void gemm_h(
    const __half* __restrict__ A, int lda,
    const __half* __restrict__ B, int ldb,
    const float* __restrict__ bias, void* __restrict__ Cv,
    int M, int N, int K)
{
    extern __shared__ uint32_t sm[];

    float* Cf = (float*)Cv;
    __half* Ch = (__half*)Cv;
    if (OP == 4) {
        const size_t zo = (size_t)blockIdx.z * K;
        A += zo; B += zo;
        Cf += (size_t)blockIdx.z * (size_t)M * N;
    }

    const int tid  = threadIdx.x;
    const int warp = tid >> 5;
    const int lane = tid & 31;
    const int g = lane >> 2;
    const int t = lane & 3;

    const int m0 = blockIdx.y * 128;
    const int n0 = blockIdx.x * 256;
    const int warp_m = (warp & 1) * 64;
    const int warp_n = (warp >> 1) * 64;

    // producers: A: (row = tid>>1, subtile = tid&1); B: row = tid, both subs
    const int arow = tid >> 1, asub = tid & 1;
    const bool aok = (m0 + arow) < M;
    const __half* Agp = A + (size_t)(m0 + arow) * lda + asub * 16;
    const __half* Bgp = B + (size_t)(n0 + tid) * ldb;
    const int aswz = swz(arow);
    const int bswz = swz(tid);

    uint32_t* const Aa = sm + asub * 1040 + arow * 8;      // + buf*2064
    uint32_t* const Bb0 = sm + 4128 + tid * 8;             // + buf*4096 (+sub*2048)

    float acc[4][8][4];
#pragma unroll
    for (int am = 0; am < 4; am++)
#pragma unroll
        for (int bn = 0; bn < 8; bn++)
#pragma unroll
            for (int i = 0; i < 4; i++) acc[am][bn][i] = 0.f;

    uint4 pA0, pA1, pB00, pB01, pB10, pB11;
    const uint4 z4 = make_uint4(0, 0, 0, 0);

#define LOAD32(k0)                                                             \
    {                                                                          \
        pA0 = aok ? *(const uint4*)(Agp + (k0))     : z4;                      \
        pA1 = aok ? *(const uint4*)(Agp + (k0) + 8) : z4;                      \
        pB00 = *(const uint4*)(Bgp + (k0));                                    \
        pB01 = *(const uint4*)(Bgp + (k0) + 8);                                \
        pB10 = *(const uint4*)(Bgp + (k0) + 16);                               \
        pB11 = *(const uint4*)(Bgp + (k0) + 24);                               \
    }

#define STORE32(buf_)                                                          \
    {                                                                          \
        uint32_t* Ad = Aa + (buf_) * 2064;                                     \
        const uint32_t* a0p = (const uint32_t*)&pA0;                           \
        const uint32_t* a1p = (const uint32_t*)&pA1;                           \
        _Pragma("unroll")                                                      \
        for (int j = 0; j < 4; j++)                                            \
            *(uint2*)&Ad[(2 * j) ^ aswz] = make_uint2(a0p[j], a1p[j]);         \
        uint32_t* Bd0 = Bb0 + (buf_) * 4096;                                   \
        uint32_t* Bd1 = Bd0 + 2048;                                            \
        const uint32_t* b00 = (const uint32_t*)&pB00;                          \
        const uint32_t* b01 = (const uint32_t*)&pB01;                          \
        const uint32_t* b10 = (const uint32_t*)&pB10;                          \
        const uint32_t* b11 = (const uint32_t*)&pB11;                          \
        _Pragma("unroll")                                                      \
        for (int j = 0; j < 4; j++) {                                          \
            *(uint2*)&Bd0[(2 * j) ^ bswz] = make_uint2(b00[j], b01[j]);        \
            *(uint2*)&Bd1[(2 * j) ^ bswz] = make_uint2(b10[j], b11[j]);        \
        }                                                                      \
    }

    LOAD32(0);
    STORE32(0);
    __syncthreads();

    int aoff[4][2], boff[8];
#pragma unroll
    for (int am = 0; am < 4; am++) {
        const int rl = warp_m + am * 16 + g;
        const int rh = rl + 8;
        aoff[am][0] = rl * 8 + ((2 * t) ^ swz(rl));
        aoff[am][1] = rh * 8 + ((2 * t) ^ swz(rh));
    }
#pragma unroll
    for (int bn = 0; bn < 8; bn++) {
        const int rn = warp_n + bn * 8 + g;
        boff[bn] = rn * 8 + ((2 * t) ^ swz(rn));
    }

    const int nstages = K >> 5;
    int buf = 0;

    for (int s = 0; s < nstages; s++) {
        const bool has_next = (s + 1 < nstages);
        if (has_next) LOAD32((s + 1) << 5);

#pragma unroll
        for (int ks2 = 0; ks2 < 2; ks2++) {
            const uint32_t* Ab = sm + buf * 2064 + ks2 * 1040;
            const uint32_t* Bb = sm + 4128 + buf * 4096 + ks2 * 2048;
            uint2 afl[4], afh[4];
#pragma unroll
            for (int am = 0; am < 4; am++) {
                afl[am] = *(const uint2*)&Ab[aoff[am][0]];
                afh[am] = *(const uint2*)&Ab[aoff[am][1]];
            }
            uint2 bf[8];
#pragma unroll
            for (int bn = 0; bn < 8; bn++) bf[bn] = *(const uint2*)&Bb[boff[bn]];

#pragma unroll
            for (int am = 0; am < 4; am++)
#pragma unroll
                for (int bn = 0; bn < 8; bn++)
                    mma_f16(acc[am][bn],
                            afl[am].x, afh[am].x, afl[am].y, afh[am].y,
                            bf[bn].x, bf[bn].y);
        }

        if (has_next) STORE32(buf ^ 1);
        __syncthreads();
        buf ^= 1;
    }
#undef LOAD32
#undef STORE32

    // epilogue
#pragma unroll
    for (int am = 0; am < 4; am++) {
        const int r0 = m0 + warp_m + am * 16 + g;
        const int r1 = r0 + 8;
#pragma unroll
        for (int bn = 0; bn < 8; bn++) {
            const int col = n0 + warp_n + bn * 8 + t * 2;
            float2 bb = make_float2(0.f, 0.f);
            if (OP != 4 && bias) bb = *(const float2*)&bias[col];
            const float* cc = acc[am][bn];
#pragma unroll
            for (int half_ = 0; half_ < 2; half_++) {
                const int r = half_ ? r1 : r0;
                if (r >= M) continue;
                float v0 = cc[2 * half_ + 0] + bb.x;
                float v1 = cc[2 * half_ + 1] + bb.y;
                if (OP == 6) {
                    v0 = v0 / (1.f + __expf(-1.702f * v0));
                    v1 = v1 / (1.f + __expf(-1.702f * v1));
                }
                if (OP == 0 || OP == 4) {
                    *(float2*)&Cf[(size_t)r * N + col] = make_float2(v0, v1);
                } else {
                    *(uint32_t*)&Ch[(size_t)r * N + col] = pack_f16(v0, v1);
                }
            }
        }
    }
}

// ===========================================================================
// fp32 -> fp16 conversion kernels
// ===========================================================================
__global__ void cvt4(const float* __restrict__ src, __half* __restrict__ dst, int n4)
{
    const int i = blockIdx.x * 256 + threadIdx.x;
    if (i >= n4) return;
    float4 v = *(const float4*)(src + i * 4);
    *(uint2*)(dst + i * 4) = make_uint2(pack_f16(v.x, v.y), pack_f16(v.z, v.w));
}

__global__ void cvt_pad(const float* __restrict__ src, __half* __restrict__ dst,
                        int cols, int colsPad, int total)
{
    const int i = blockIdx.x * 256 + threadIdx.x;
    if (i >= total) return;
    const int r = i / colsPad, c = i % colsPad;
    dst[i] = (c < cols) ? __float2half(src[(size_t)r * cols + c]) : __half(0.f);
}

// ===========================================================================
// split-K reduce: MODE 0: dst=sum+bias (f32); 1: dst+=sum+bias (f32);
//                 4: dst=GELU(sum+bias) (f16)
// ===========================================================================
template <int NP, int MODE>
__global__ void reduce_k(const float* __restrict__ part,
                         const float* __restrict__ bias,
                         void* __restrict__ dstv, int total, int ncols)
{
    const int i = blockIdx.x * 256 + threadIdx.x;
    if (i >= total) return;
    float s = bias[i % ncols];
#pragma unroll
    for (int c = 0; c < NP; c++) s += part[(size_t)c * total + i];
    if (MODE == 0) ((float*)dstv)[i] = s;
    else if (MODE == 1) ((float*)dstv)[i] += s;
    else ((__half*)dstv)[i] =
        __float2half(0.5f * s * (1.f + erff(s * 0.7071067811865475f)));
}

// ---------------------------------------------------------------------------
// RoPE cos/sin tables
// ---------------------------------------------------------------------------
__global__ void rope_table(const float* __restrict__ rotary,
                           float* __restrict__ rcos, float* __restrict__ rsin)
{
    const int i = blockIdx.x * 256 + threadIdx.x;
    if (i >= S_TOK * 40) return;
    float c, s;
    sincosf(rotary[i], &s, &c);
    rcos[i] = c;
    rsin[i] = s;
}

// ---------------------------------------------------------------------------
// LayerNorm (fp32 in, fp16 out)
// ---------------------------------------------------------------------------
__global__ __launch_bounds__(256) void ln_kernel(
    const float* __restrict__ x, const float* __restrict__ w,
    const float* __restrict__ b, __half* __restrict__ y)
{
    const int row = blockIdx.x;
    const int tid = threadIdx.x;
    const float* xr = x + (size_t)row * DMODEL;

    float s = 0.f, sq = 0.f;
#pragma unroll
    for (int i = 0; i < DMODEL / 256; i++) {
        float v = xr[tid + i * 256];
        s += v; sq += v * v;
    }
#pragma unroll
    for (int o = 16; o > 0; o >>= 1) {
        s  += __shfl_xor_sync(0xffffffffu, s, o);
        sq += __shfl_xor_sync(0xffffffffu, sq, o);
    }
    __shared__ float ws[8], wsq[8];
    if ((tid & 31) == 0) { ws[tid >> 5] = s; wsq[tid >> 5] = sq; }
    __syncthreads();
    __shared__ float s_mu, s_rstd;
    if (tid == 0) {
        float ts = 0.f, tsq = 0.f;
        for (int i = 0; i < 8; i++) { ts += ws[i]; tsq += wsq[i]; }
        float mu = ts / DMODEL;
        float var = tsq / DMODEL - mu * mu;
        s_mu = mu;
        s_rstd = rsqrtf(var + 1e-6f);
    }
    __syncthreads();
    float mu = s_mu, rstd = s_rstd;
    __half* yr = y + (size_t)row * DMODEL;
#pragma unroll
    for (int i = 0; i < DMODEL / 256; i++) {
        int c = tid + i * 256;
        yr[c] = __float2half((xr[c] - mu) * rstd * w[c] + b[c]);
    }
}

// ===========================================================================
// Attention: FA2-style fp16 mma (fp32 accum), 128 thr = 4 warps, fused RoPE.
// qkv/out buffers fp16.
// ===========================================================================
#define AT_STRIDE 88

__device__ __forceinline__ void ldsm4(uint32_t* r, uint32_t addr) {
    asm volatile("ldmatrix.sync.aligned.m8n8.x4.shared.b16 {%0,%1,%2,%3}, [%4];"
                 : "=r"(r[0]), "=r"(r[1]), "=r"(r[2]), "=r"(r[3]) : "r"(addr));
}
__device__ __forceinline__ void ldsm4t(uint32_t* r, uint32_t addr) {
    asm volatile("ldmatrix.sync.aligned.m8n8.x4.trans.shared.b16 {%0,%1,%2,%3}, [%4];"
                 : "=r"(r[0]), "=r"(r[1]), "=r"(r[2]), "=r"(r[3]) : "r"(addr));
}

__device__ __forceinline__ void load_rope_half_h(
    const __half* __restrict__ src, const __half* __restrict__ srco,
    const float* __restrict__ tc, const float* __restrict__ ts,
    float sgn, float scale, __half* dst)
{
#pragma unroll
    for (int j = 0; j < 10; j++) {
        uint2 rv = *(const uint2*)(src + j * 4);
        uint2 rw = *(const uint2*)(srco + j * 4);
        float2 v0 = __half22float2(*(__half2*)&rv.x);
        float2 v1 = __half22float2(*(__half2*)&rv.y);
        float2 w0 = __half22float2(*(__half2*)&rw.x);
        float2 w1 = __half22float2(*(__half2*)&rw.y);
        float4 c = *(const float4*)(tc + j * 4);
        float4 s = *(const float4*)(ts + j * 4);
        float o0 = (v0.x * c.x + sgn * w0.x * s.x) * scale;
        float o1 = (v0.y * c.y + sgn * w0.y * s.y) * scale;
        float o2 = (v1.x * c.z + sgn * w1.x * s.z) * scale;
        float o3 = (v1.y * c.w + sgn * w1.y * s.w) * scale;
        *(uint2*)(dst + j * 4) = make_uint2(pack_f16(o0, o1), pack_f16(o2, o3));
    }
}

__global__ __launch_bounds__(128) void attn_f16(
    const __half* __restrict__ qkv, const int* __restrict__ seg,
    const float* __restrict__ rcos, const float* __restrict__ rsin,
    __half* __restrict__ out)
{
    __shared__ __half Qs[64 * AT_STRIDE];
    __shared__ __half Ks[64 * AT_STRIDE];
    __shared__ __half Vs[64 * AT_STRIDE];

    const int head = blockIdx.x;
    const int q0   = blockIdx.y * 64;
    const int tid  = threadIdx.x;
    const int w    = tid >> 5;
    const int lane = tid & 31;
    const int g    = lane >> 2;
    const int t    = lane & 3;

    const float scale = 0.11180339887498949f;

    uint32_t qb, kb, vb;
    asm("{ .reg .u64 u; cvta.to.shared.u64 u, %1; cvt.u32.u64 %0, u; }" : "=r"(qb) : "l"(Qs));
    asm("{ .reg .u64 u; cvta.to.shared.u64 u, %1; cvt.u32.u64 %0, u; }" : "=r"(kb) : "l"(Ks));
    asm("{ .reg .u64 u; cvta.to.shared.u64 u, %1; cvt.u32.u64 %0, u; }" : "=r"(vb) : "l"(Vs));

    const int lrow = tid >> 1;
    const int lh   = tid & 1;
    const float sgn = lh ? 1.f : -1.f;

    {
        const __half* base = qkv + (size_t)(q0 + lrow) * (3 * DMODEL) + head * HDIM;
        load_rope_half_h(base + lh * 40, base + (1 - lh) * 40,
                         rcos + (q0 + lrow) * 40, rsin + (q0 + lrow) * 40,
                         sgn, scale, Qs + lrow * AT_STRIDE + lh * 40);
    }

    float m[2] = {-1e30f, -1e30f};
    float l[2] = {0.f, 0.f};
    float oacc[10][4];
#pragma unroll
    for (int j = 0; j < 10; j++)
#pragma unroll
        for (int i = 0; i < 4; i++) oacc[j][i] = 0.f;

    const int myseg = seg[q0];

    const uint32_t lrow16 = (uint32_t)(lane & 15);
    const uint32_t lhi16  = (uint32_t)(lane >> 4) * 16;
    const uint32_t q_addr0 = qb + (w * 16 + lrow16) * (AT_STRIDE * 2) + lhi16;

    __syncthreads();

    for (int c0 = 0; c0 < S_TOK; c0 += 64) {
        if (seg[c0] != myseg) continue;

        {
            const __half* baseK = qkv + (size_t)(c0 + lrow) * (3 * DMODEL) + DMODEL + head * HDIM;
            load_rope_half_h(baseK + lh * 40, baseK + (1 - lh) * 40,
                             rcos + (c0 + lrow) * 40, rsin + (c0 + lrow) * 40,
                             sgn, 1.f, Ks + lrow * AT_STRIDE + lh * 40);
            const __half* srcV = baseK + DMODEL + lh * 40;
            __half* dV = Vs + lrow * AT_STRIDE + lh * 40;
#pragma unroll
            for (int j = 0; j < 10; j++)
                *(uint2*)(dV + j * 4) = *(const uint2*)(srcV + j * 4);
        }
        __syncthreads();

        float sacc[8][4];
#pragma unroll
        for (int j = 0; j < 8; j++)
#pragma unroll
            for (int i = 0; i < 4; i++) sacc[j][i] = 0.f;

#pragma unroll
        for (int ks = 0; ks < 5; ks++) {
            uint32_t aq[4];
            ldsm4(aq, q_addr0 + ks * 32);
#pragma unroll
            for (int nb = 0; nb < 4; nb++) {
                uint32_t kr[4];
                ldsm4(kr, kb + (nb * 16 + lrow16) * (AT_STRIDE * 2) + lhi16 + ks * 32);
                mma_f16(sacc[2 * nb],     aq[0], aq[1], aq[2], aq[3], kr[0], kr[2]);
                mma_f16(sacc[2 * nb + 1], aq[0], aq[1], aq[2], aq[3], kr[1], kr[3]);
            }
        }

        float cs[2];
#pragma unroll
        for (int i = 0; i < 2; i++) {
            float cm = -1e30f;
#pragma unroll
            for (int j = 0; j < 8; j++) {
                cm = fmaxf(cm, sacc[j][2 * i]);
                cm = fmaxf(cm, sacc[j][2 * i + 1]);
            }
            cm = fmaxf(cm, __shfl_xor_sync(0xffffffffu, cm, 1));
            cm = fmaxf(cm, __shfl_xor_sync(0xffffffffu, cm, 2));
            const float nm = fmaxf(m[i], cm);
            cs[i] = __expf(m[i] - nm);
            m[i] = nm;
            float ps = 0.f;
#pragma unroll
            for (int j = 0; j < 8; j++) {
                float p0 = __expf(sacc[j][2 * i] - nm);
                float p1 = __expf(sacc[j][2 * i + 1] - nm);
                sacc[j][2 * i] = p0; sacc[j][2 * i + 1] = p1;
                ps += p0 + p1;
            }
            ps += __shfl_xor_sync(0xffffffffu, ps, 1);
            ps += __shfl_xor_sync(0xffffffffu, ps, 2);
            l[i] = l[i] * cs[i] + ps;
        }
#pragma unroll
        for (int j = 0; j < 10; j++) {
            oacc[j][0] *= cs[0]; oacc[j][1] *= cs[0];
            oacc[j][2] *= cs[1]; oacc[j][3] *= cs[1];
        }

#pragma unroll
        for (int ks = 0; ks < 4; ks++) {
            uint32_t pp[4];
            pp[0] = pack_f16(sacc[2 * ks][0],     sacc[2 * ks][1]);
            pp[1] = pack_f16(sacc[2 * ks][2],     sacc[2 * ks][3]);
            pp[2] = pack_f16(sacc[2 * ks + 1][0], sacc[2 * ks + 1][1]);
            pp[3] = pack_f16(sacc[2 * ks + 1][2], sacc[2 * ks + 1][3]);
#pragma unroll
            for (int db = 0; db < 5; db++) {
                uint32_t vr[4];
                ldsm4t(vr, vb + (ks * 16 + lrow16) * (AT_STRIDE * 2) + db * 32 + lhi16);
                mma_f16(oacc[2 * db],     pp[0], pp[1], pp[2], pp[3], vr[0], vr[1]);
                mma_f16(oacc[2 * db + 1], pp[0], pp[1], pp[2], pp[3], vr[2], vr[3]);
            }
        }
        __syncthreads();
    }

    const float inv0 = 1.f / l[0];
    const float inv1 = 1.f / l[1];
    const int r0 = q0 + w * 16 + g;
#pragma unroll
    for (int j = 0; j < 10; j++) {
        const int d = head * HDIM + j * 8 + t * 2;
        *(uint32_t*)&out[(size_t)r0 * DMODEL + d] =
            pack_f16(oacc[j][0] * inv0, oacc[j][1] * inv0);
        *(uint32_t*)&out[(size_t)(r0 + 8) * DMODEL + d] =
            pack_f16(oacc[j][2] * inv1, oacc[j][3] * inv1);
    }
}

// ---------------------------------------------------------------------------
// Host side
// ---------------------------------------------------------------------------
static inline void run_gemm(int op, const __half* A, int lda, const __half* B, int ldb,
                            const float* bias, void* C, int M, int N, int K)
{
    dim3 grid(N / 256, (M + 127) / 128);
    switch (op) {
        case 0: gemm_h<0><<<grid, 256, GEMM_SMEM_BYTES>>>(A, lda, B, ldb, bias, C, M, N, K); break;
        case 5: gemm_h<5><<<grid, 256, GEMM_SMEM_BYTES>>>(A, lda, B, ldb, bias, C, M, N, K); break;
        case 6: gemm_h<6><<<grid, 256, GEMM_SMEM_BYTES>>>(A, lda, B, ldb, bias, C, M, N, K); break;
    }
}

static inline void run_splitk(int parts, const __half* A, int ld,
                              const __half* B, float* part_buf,
                              int M, int N, int Kfull)
{
    dim3 grid(N / 256, (M + 127) / 128, parts);
    gemm_h<4><<<grid, 256, GEMM_SMEM_BYTES>>>(A, ld, B, ld, nullptr,
                                              part_buf, M, N, Kfull / parts);
}

extern "C" void kernel_launch(void* const* d_in, const int* in_sizes, int n_in,
                              void* d_out, int out_size)
{
    const float* pixels  = (const float*)d_in[0];
    const float* rotary  = (const float*)d_in[1];
    const int*   seg_ids = (const int*)d_in[2];
    const float* proj_w  = (const float*)d_in[3];
    const float* ln1_w   = (const float*)d_in[4];
    const float* ln1_b   = (const float*)d_in[5];
    const float* qkv_w   = (const float*)d_in[6];
    const float* qkv_b   = (const float*)d_in[7];
    const float* po_w    = (const float*)d_in[8];
    const float* po_b    = (const float*)d_in[9];
    const float* ln2_w   = (const float*)d_in[10];
    const float* ln2_b   = (const float*)d_in[11];
    const float* fc1_w   = (const float*)d_in[12];
    const float* fc1_b   = (const float*)d_in[13];
    const float* fc2_w   = (const float*)d_in[14];
    const float* fc2_b   = (const float*)d_in[15];
    const float* mln_w   = (const float*)d_in[16];
    const float* mln_b   = (const float*)d_in[17];
    const float* m1_w    = (const float*)d_in[18];
    const float* m1_b    = (const float*)d_in[19];
    const float* m2_w    = (const float*)d_in[20];
    const float* m2_b    = (const float*)d_in[21];
    float* out = (float*)d_out;

    float *x, *part, *rcos, *rsin;
    __half *pixh, *projwh, *qkvwh, *powh, *fc1wh, *fc2wh, *m1wh, *m2wh;
    __half *lnh, *qkvh, *atth, *bigh;
    cudaGetSymbolAddress((void**)&x,      g_x);
    cudaGetSymbolAddress((void**)&part,   g_part);
    cudaGetSymbolAddress((void**)&rcos,   g_rcos);
    cudaGetSymbolAddress((void**)&rsin,   g_rsin);
    cudaGetSymbolAddress((void**)&pixh,   g_pix_h);
    cudaGetSymbolAddress((void**)&projwh, g_projw_h);
    cudaGetSymbolAddress((void**)&qkvwh,  g_qkvw_h);
    cudaGetSymbolAddress((void**)&powh,   g_pow_h);
    cudaGetSymbolAddress((void**)&fc1wh,  g_fc1w_h);
    cudaGetSymbolAddress((void**)&fc2wh,  g_fc2w_h);
    cudaGetSymbolAddress((void**)&m1wh,   g_m1w_h);
    cudaGetSymbolAddress((void**)&m2wh,   g_m2w_h);
    cudaGetSymbolAddress((void**)&lnh,    g_ln_h);
    cudaGetSymbolAddress((void**)&qkvh,   g_qkv_h);
    cudaGetSymbolAddress((void**)&atth,   g_att_h);
    cudaGetSymbolAddress((void**)&bigh,   g_big_h);

    cudaFuncSetAttribute(gemm_h<0>, cudaFuncAttributeMaxDynamicSharedMemorySize, GEMM_SMEM_BYTES);
    cudaFuncSetAttribute(gemm_h<4>, cudaFuncAttributeMaxDynamicSharedMemorySize, GEMM_SMEM_BYTES);
    cudaFuncSetAttribute(gemm_h<5>, cudaFuncAttributeMaxDynamicSharedMemorySize, GEMM_SMEM_BYTES);
    cudaFuncSetAttribute(gemm_h<6>, cudaFuncAttributeMaxDynamicSharedMemorySize, GEMM_SMEM_BYTES);

    // weight / input conversions (once per launch)
    {
        const int tp = S_TOK * KPAD;
        cvt_pad<<<(tp + 255) / 256, 256>>>(pixels, pixh, 1176, KPAD, tp);
        const int tw = DMODEL * KPAD;
        cvt_pad<<<(tw + 255) / 256, 256>>>(proj_w, projwh, 1176, KPAD, tw);
        int n;
        n = DEPTH * 3 * DMODEL * DMODEL; cvt4<<<(n / 4 + 255) / 256, 256>>>(qkv_w, qkvwh, n / 4);
        n = DEPTH * DMODEL * DMODEL;     cvt4<<<(n / 4 + 255) / 256, 256>>>(po_w,  powh,  n / 4);
        n = DEPTH * 4 * DMODEL * DMODEL; cvt4<<<(n / 4 + 255) / 256, 256>>>(fc1_w, fc1wh, n / 4);
        n = DEPTH * DMODEL * 4 * DMODEL; cvt4<<<(n / 4 + 255) / 256, 256>>>(fc2_w, fc2wh, n / 4);
        n = 4 * DMODEL * 4 * DMODEL;     cvt4<<<(n / 4 + 255) / 256, 256>>>(m1_w,  m1wh,  n / 4);
        n = 1536 * 4 * DMODEL;           cvt4<<<(n / 4 + 255) / 256, 256>>>(m2_w,  m2wh,  n / 4);
    }
    rope_table<<<(S_TOK * 40 + 255) / 256, 256>>>(rotary, rcos, rsin);

    // patch projection: x = pixels @ proj_w^T (fp32 out)
    run_gemm(0, pixh, KPAD, projwh, KPAD, nullptr, x, S_TOK, DMODEL, KPAD);

    for (int l = 0; l < DEPTH; l++) {
        ln_kernel<<<S_TOK, 256>>>(x, ln1_w + l * DMODEL, ln1_b + l * DMODEL, lnh);
        run_gemm(5, lnh, DMODEL, qkvwh + (size_t)l * 3 * DMODEL * DMODEL, DMODEL,
                 qkv_b + (size_t)l * 3 * DMODEL, qkvh, S_TOK, 3 * DMODEL, DMODEL);
        {
            dim3 grid(NHEAD, S_TOK / 64);
            attn_f16<<<grid, 128>>>(qkvh, seg_ids, rcos, rsin, atth);
        }
        // po: split-K x4, reduce adds bias into x
        run_splitk(4, atth, DMODEL, powh + (size_t)l * DMODEL * DMODEL, part,
                   S_TOK, DMODEL, DMODEL);
        reduce_k<4, 1><<<(S_TOK * DMODEL + 255) / 256, 256>>>(
            part, po_b + (size_t)l * DMODEL, x, S_TOK * DMODEL, DMODEL);

        ln_kernel<<<S_TOK, 256>>>(x, ln2_w + l * DMODEL, ln2_b + l * DMODEL, lnh);
        run_gemm(6, lnh, DMODEL, fc1wh + (size_t)l * 4 * DMODEL * DMODEL, DMODEL,
                 fc1_b + (size_t)l * 4 * DMODEL, bigh, S_TOK, 4 * DMODEL, DMODEL);
        // fc2: split-K x4
        run_splitk(4, bigh, 4 * DMODEL,
                   fc2wh + (size_t)l * DMODEL * 4 * DMODEL, part,
                   S_TOK, DMODEL, 4 * DMODEL);
        reduce_k<4, 1><<<(S_TOK * DMODEL + 255) / 256, 256>>>(
            part, fc2_b + (size_t)l * DMODEL, x, S_TOK * DMODEL, DMODEL);
    }

    ln_kernel<<<S_TOK, 256>>>(x, mln_w, mln_b, lnh);
    // m1: split-K x4, GELU->fp16 in reduce -> bigh
    run_splitk(4, lnh, 4 * DMODEL, m1wh, part, S_TOK / 4, 4 * DMODEL, 4 * DMODEL);
    reduce_k<4, 4><<<(320 * 4 * DMODEL + 255) / 256, 256>>>(
        part, m1_b, bigh, 320 * 4 * DMODEL, 4 * DMODEL);
    // m2: split-K x8 -> reduce -> out (fp32)
    run_splitk(8, bigh, 4 * DMODEL, m2wh, part, 320, 1536, 4 * DMODEL);
    reduce_k<8, 0><<<(320 * 1536 + 255) / 256, 256>>>(
        part, m2_b, out, 320 * 1536, 1536);
}

// round 13
// speedup vs baseline: 1.4342x; 1.0191x over previous
#include <cuda_runtime.h>
#include <cuda_bf16.h>
#include <cuda_fp16.h>
#include <math.h>
#include <stdint.h>

// ---------------------------------------------------------------------------
// VisionModel: S=1280, D=1280, H=16, HD=80, DEPTH=4. Output (320,1536) fp32.
// All GEMM operands staged fp16 (single merged conversion kernel).
// GEMM: 128x256 block, 8 warps x 64x64, BK=32. FA2 attention w/ fused RoPE.
// ---------------------------------------------------------------------------

#define S_TOK 1280
#define DMODEL 1280
#define NHEAD 16
#define HDIM 80
#define DEPTH 4
#define KPAD 1184   // pixels/proj K padded 1176 -> 1184 (mult of 32)

// fp16 staging buffers
__device__ __half g_pix_h [S_TOK * KPAD];
__device__ __half g_projw_h[DMODEL * KPAD];
__device__ __half g_qkvw_h[DEPTH * 3 * DMODEL * DMODEL];
__device__ __half g_pow_h [DEPTH * DMODEL * DMODEL];
__device__ __half g_fc1w_h[DEPTH * 4 * DMODEL * DMODEL];
__device__ __half g_fc2w_h[DEPTH * DMODEL * 4 * DMODEL];
__device__ __half g_m1w_h [4 * DMODEL * 4 * DMODEL];
__device__ __half g_m2w_h [1536 * 4 * DMODEL];
__device__ __half g_ln_h  [S_TOK * DMODEL];
__device__ __half g_qkv_h [S_TOK * 3 * DMODEL];
__device__ __half g_att_h [S_TOK * DMODEL];
__device__ __half g_big_h [S_TOK * 4 * DMODEL];
// fp32
__device__ float g_x[S_TOK * DMODEL];
__device__ float g_part[4 * DMODEL * S_TOK];
__device__ float g_rcos[S_TOK * 40];
__device__ float g_rsin[S_TOK * 40];

// ===========================================================================

__device__ __forceinline__ uint32_t pack_f16(float lo, float hi) {
    uint32_t r;
    asm("cvt.rn.f16x2.f32 %0, %1, %2;" : "=r"(r) : "f"(hi), "f"(lo));
    return r;
}

__device__ __forceinline__ void mma_f16(float* c,
    uint32_t a0, uint32_t a1, uint32_t a2, uint32_t a3,
    uint32_t b0, uint32_t b1)
{
    asm volatile(
        "mma.sync.aligned.m16n8k16.row.col.f32.f16.f16.f32 "
        "{%0,%1,%2,%3},{%4,%5,%6,%7},{%8,%9},{%0,%1,%2,%3};"
        : "+f"(c[0]), "+f"(c[1]), "+f"(c[2]), "+f"(c[3])
        : "r"(a0), "r"(a1), "r"(a2), "r"(a3), "r"(b0), "r"(b1));
}

__device__ __forceinline__ int swz(int r) { return ((r ^ (r >> 2)) & 3) << 1; }

// ===========================================================================
// fp16 GEMM (identical to round-12 winner): 128x256 block, 8 warps, BK=32.
// OP 0: fp32 out; 4: split-K fp32 partial; 5: fp16 out+bias; 6: fp16 SiLU+bias
// ===========================================================================
#define GEMM_SMEM_BYTES ((4128 + 8192) * 4)

template <int OP>
__global__ __launch_bounds__(256) void gemm_h(
    const __half* __restrict__ A, int lda,
    const __half* __restrict__ B, int ldb,
    const float* __restrict__ bias, void* __restrict__ Cv,
    int M, int N, int K)
{
    extern __shared__ uint32_t sm[];

    float* Cf = (float*)Cv;
    __half* Ch = (__half*)Cv;
    if (OP == 4) {
        const size_t zo = (size_t)blockIdx.z * K;
        A += zo; B += zo;
        Cf += (size_t)blockIdx.z * (size_t)M * N;
    }

    const int tid  = threadIdx.x;
    const int warp = tid >> 5;
    const int lane = tid & 31;
    const int g = lane >> 2;
    const int t = lane & 3;

    const int m0 = blockIdx.y * 128;
    const int n0 = blockIdx.x * 256;
    const int warp_m = (warp & 1) * 64;
    const int warp_n = (warp >> 1) * 64;

    const int arow = tid >> 1, asub = tid & 1;
    const bool aok = (m0 + arow) < M;
    const __half* Agp = A + (size_t)(m0 + arow) * lda + asub * 16;
    const __half* Bgp = B + (size_t)(n0 + tid) * ldb;
    const int aswz = swz(arow);
    const int bswz = swz(tid);

    uint32_t* const Aa = sm + asub * 1040 + arow * 8;
    uint32_t* const Bb0 = sm + 4128 + tid * 8;

    float acc[4][8][4];
#pragma unroll
    for (int am = 0; am < 4; am++)
#pragma unroll
        for (int bn = 0; bn < 8; bn++)
#pragma unroll
            for (int i = 0; i < 4; i++) acc[am][bn][i] = 0.f;

    uint4 pA0, pA1, pB00, pB01, pB10, pB11;
    const uint4 z4 = make_uint4(0, 0, 0, 0);

#define LOAD32(k0)                                                             \
    {                                                                          \
        pA0 = aok ? *(const uint4*)(Agp + (k0))     : z4;                      \
        pA1 = aok ? *(const uint4*)(Agp + (k0) + 8) : z4;                      \
        pB00 = *(const uint4*)(Bgp + (k0));                                    \
        pB01 = *(const uint4*)(Bgp + (k0) + 8);                                \
        pB10 = *(const uint4*)(Bgp + (k0) + 16);                               \
        pB11 = *(const uint4*)(Bgp + (k0) + 24);                               \
    }

#define STORE32(buf_)                                                          \
    {                                                                          \
        uint32_t* Ad = Aa + (buf_) * 2064;                                     \
        const uint32_t* a0p = (const uint32_t*)&pA0;                           \
        const uint32_t* a1p = (const uint32_t*)&pA1;                           \
        _Pragma("unroll")                                                      \
        for (int j = 0; j < 4; j++)                                            \
            *(uint2*)&Ad[(2 * j) ^ aswz] = make_uint2(a0p[j], a1p[j]);         \
        uint32_t* Bd0 = Bb0 + (buf_) * 4096;                                   \
        uint32_t* Bd1 = Bd0 + 2048;                                            \
        const uint32_t* b00 = (const uint32_t*)&pB00;                          \
        const uint32_t* b01 = (const uint32_t*)&pB01;                          \
        const uint32_t* b10 = (const uint32_t*)&pB10;                          \
        const uint32_t* b11 = (const uint32_t*)&pB11;                          \
        _Pragma("unroll")                                                      \
        for (int j = 0; j < 4; j++) {                                          \
            *(uint2*)&Bd0[(2 * j) ^ bswz] = make_uint2(b00[j], b01[j]);        \
            *(uint2*)&Bd1[(2 * j) ^ bswz] = make_uint2(b10[j], b11[j]);        \
        }                                                                      \
    }

    LOAD32(0);
    STORE32(0);
    __syncthreads();

    int aoff[4][2], boff[8];
#pragma unroll
    for (int am = 0; am < 4; am++) {
        const int rl = warp_m + am * 16 + g;
        const int rh = rl + 8;
        aoff[am][0] = rl * 8 + ((2 * t) ^ swz(rl));
        aoff[am][1] = rh * 8 + ((2 * t) ^ swz(rh));
    }
#pragma unroll
    for (int bn = 0; bn < 8; bn++) {
        const int rn = warp_n + bn * 8 + g;
        boff[bn] = rn * 8 + ((2 * t) ^ swz(rn));
    }

    const int nstages = K >> 5;
    int buf = 0;

    for (int s = 0; s < nstages; s++) {
        const bool has_next = (s + 1 < nstages);
        if (has_next) LOAD32((s + 1) << 5);

#pragma unroll
        for (int ks2 = 0; ks2 < 2; ks2++) {
            const uint32_t* Ab = sm + buf * 2064 + ks2 * 1040;
            const uint32_t* Bb = sm + 4128 + buf * 4096 + ks2 * 2048;
            uint2 afl[4], afh[4];
#pragma unroll
            for (int am = 0; am < 4; am++) {
                afl[am] = *(const uint2*)&Ab[aoff[am][0]];
                afh[am] = *(const uint2*)&Ab[aoff[am][1]];
            }
            uint2 bf[8];
#pragma unroll
            for (int bn = 0; bn < 8; bn++) bf[bn] = *(const uint2*)&Bb[boff[bn]];

#pragma unroll
            for (int am = 0; am < 4; am++)
#pragma unroll
                for (int bn = 0; bn < 8; bn++)
                    mma_f16(acc[am][bn],
                            afl[am].x, afh[am].x, afl[am].y, afh[am].y,
                            bf[bn].x, bf[bn].y);
        }

        if (has_next) STORE32(buf ^ 1);
        __syncthreads();
        buf ^= 1;
    }
#undef LOAD32
#undef STORE32

#pragma unroll
    for (int am = 0; am < 4; am++) {
        const int r0 = m0 + warp_m + am * 16 + g;
        const int r1 = r0 + 8;
#pragma unroll
        for (int bn = 0; bn < 8; bn++) {
            const int col = n0 + warp_n + bn * 8 + t * 2;
            float2 bb = make_float2(0.f, 0.f);
            if (OP != 4 && bias) bb = *(const float2*)&bias[col];
            const float* cc = acc[am][bn];
#pragma unroll
            for (int half_ = 0; half_ < 2; half_++) {
                const int r = half_ ? r1 : r0;
                if (r >= M) continue;
                float v0 = cc[2 * half_ + 0] + bb.x;
                float v1 = cc[2 * half_ + 1] + bb.y;
                if (OP == 6) {
                    v0 = v0 / (1.f + __expf(-1.702f * v0));
                    v1 = v1 / (1.f + __expf(-1.702f * v1));
                }
                if (OP == 0 || OP == 4) {
                    *(float2*)&Cf[(size_t)r * N + col] = make_float2(v0, v1);
                } else {
                    *(uint32_t*)&Ch[(size_t)r * N + col] = pack_f16(v0, v1);
                }
            }
        }
    }
}

// ===========================================================================
// Merged weight conversion: 6 segments, 8 elems/thread (float4 x2 -> uint4).
// Offsets e0..e5 are cumulative END indices in 8-element units.
// ===========================================================================
__global__ void cvt_merged(
    const float* __restrict__ s0, __half* __restrict__ d0, long long e0,
    const float* __restrict__ s1, __half* __restrict__ d1, long long e1,
    const float* __restrict__ s2, __half* __restrict__ d2, long long e2,
    const float* __restrict__ s3, __half* __restrict__ d3, long long e3,
    const float* __restrict__ s4, __half* __restrict__ d4, long long e4,
    const float* __restrict__ s5, __half* __restrict__ d5, long long e5)
{
    const long long i = (long long)blockIdx.x * 256 + threadIdx.x;
    if (i >= e5) return;
    const float* s; __half* d; long long base;
    if      (i < e0) { s = s0; d = d0; base = 0;  }
    else if (i < e1) { s = s1; d = d1; base = e0; }
    else if (i < e2) { s = s2; d = d2; base = e1; }
    else if (i < e3) { s = s3; d = d3; base = e2; }
    else if (i < e4) { s = s4; d = d4; base = e3; }
    else             { s = s5; d = d5; base = e4; }
    const long long j = (i - base) * 8;
    const float4 v0 = *(const float4*)(s + j);
    const float4 v1 = *(const float4*)(s + j + 4);
    uint4 o;
    o.x = pack_f16(v0.x, v0.y); o.y = pack_f16(v0.z, v0.w);
    o.z = pack_f16(v1.x, v1.y); o.w = pack_f16(v1.z, v1.w);
    *(uint4*)(d + j) = o;
}

__global__ void cvt_pad(const float* __restrict__ src, __half* __restrict__ dst,
                        int cols, int colsPad, int total)
{
    const int i = blockIdx.x * 256 + threadIdx.x;
    if (i >= total) return;
    const int r = i / colsPad, c = i % colsPad;
    dst[i] = (c < cols) ? __float2half(src[(size_t)r * cols + c]) : __half(0.f);
}

// ===========================================================================
// split-K reduce, 4 elems/thread. MODE 0: f32 =; 1: f32 +=; 4: f16 GELU.
// Requires total % 4 == 0 and ncols % 4 == 0 (true for all users).
// ===========================================================================
template <int NP, int MODE>
__global__ void reduce_k(const float* __restrict__ part,
                         const float* __restrict__ bias,
                         void* __restrict__ dstv, int total, int ncols)
{
    const int i = blockIdx.x * 256 + threadIdx.x;
    const int idx = i * 4;
    if (idx >= total) return;
    float4 s = *(const float4*)&bias[idx % ncols];
#pragma unroll
    for (int c = 0; c < NP; c++) {
        const float4 p = *(const float4*)&part[(size_t)c * total + idx];
        s.x += p.x; s.y += p.y; s.z += p.z; s.w += p.w;
    }
    if (MODE == 0) {
        *(float4*)&((float*)dstv)[idx] = s;
    } else if (MODE == 1) {
        float4 d = *(const float4*)&((float*)dstv)[idx];
        d.x += s.x; d.y += s.y; d.z += s.z; d.w += s.w;
        *(float4*)&((float*)dstv)[idx] = d;
    } else {
        const float g0 = 0.5f * s.x * (1.f + erff(s.x * 0.7071067811865475f));
        const float g1 = 0.5f * s.y * (1.f + erff(s.y * 0.7071067811865475f));
        const float g2 = 0.5f * s.z * (1.f + erff(s.z * 0.7071067811865475f));
        const float g3 = 0.5f * s.w * (1.f + erff(s.w * 0.7071067811865475f));
        *(uint2*)&((__half*)dstv)[idx] =
            make_uint2(pack_f16(g0, g1), pack_f16(g2, g3));
    }
}

// ---------------------------------------------------------------------------
// RoPE cos/sin tables
// ---------------------------------------------------------------------------
__global__ void rope_table(const float* __restrict__ rotary,
                           float* __restrict__ rcos, float* __restrict__ rsin)
{
    const int i = blockIdx.x * 256 + threadIdx.x;
    if (i >= S_TOK * 40) return;
    float c, s;
    sincosf(rotary[i], &s, &c);
    rcos[i] = c;
    rsin[i] = s;
}

// ---------------------------------------------------------------------------
// LayerNorm (fp32 in, fp16 out)
// ---------------------------------------------------------------------------
__global__ __launch_bounds__(256) void ln_kernel(
    const float* __restrict__ x, const float* __restrict__ w,
    const float* __restrict__ b, __half* __restrict__ y)
{
    const int row = blockIdx.x;
    const int tid = threadIdx.x;
    const float* xr = x + (size_t)row * DMODEL;

    float s = 0.f, sq = 0.f;
#pragma unroll
    for (int i = 0; i < DMODEL / 256; i++) {
        float v = xr[tid + i * 256];
        s += v; sq += v * v;
    }
#pragma unroll
    for (int o = 16; o > 0; o >>= 1) {
        s  += __shfl_xor_sync(0xffffffffu, s, o);
        sq += __shfl_xor_sync(0xffffffffu, sq, o);
    }
    __shared__ float ws[8], wsq[8];
    if ((tid & 31) == 0) { ws[tid >> 5] = s; wsq[tid >> 5] = sq; }
    __syncthreads();
    __shared__ float s_mu, s_rstd;
    if (tid == 0) {
        float ts = 0.f, tsq = 0.f;
        for (int i = 0; i < 8; i++) { ts += ws[i]; tsq += wsq[i]; }
        float mu = ts / DMODEL;
        float var = tsq / DMODEL - mu * mu;
        s_mu = mu;
        s_rstd = rsqrtf(var + 1e-6f);
    }
    __syncthreads();
    float mu = s_mu, rstd = s_rstd;
    __half* yr = y + (size_t)row * DMODEL;
#pragma unroll
    for (int i = 0; i < DMODEL / 256; i++) {
        int c = tid + i * 256;
        yr[c] = __float2half((xr[c] - mu) * rstd * w[c] + b[c]);
    }
}

// ===========================================================================
// Attention: FA2-style fp16 mma (fp32 accum), 128 thr = 4 warps, fused RoPE.
// ===========================================================================
#define AT_STRIDE 88

__device__ __forceinline__ void ldsm4(uint32_t* r, uint32_t addr) {
    asm volatile("ldmatrix.sync.aligned.m8n8.x4.shared.b16 {%0,%1,%2,%3}, [%4];"
                 : "=r"(r[0]), "=r"(r[1]), "=r"(r[2]), "=r"(r[3]) : "r"(addr));
}
__device__ __forceinline__ void ldsm4t(uint32_t* r, uint32_t addr) {
    asm volatile("ldmatrix.sync.aligned.m8n8.x4.trans.shared.b16 {%0,%1,%2,%3}, [%4];"
                 : "=r"(r[0]), "=r"(r[1]), "=r"(r[2]), "=r"(r[3]) : "r"(addr));
}

__device__ __forceinline__ void load_rope_half_h(
    const __half* __restrict__ src, const __half* __restrict__ srco,
    const float* __restrict__ tc, const float* __restrict__ ts,
    float sgn, float scale, __half* dst)
{
#pragma unroll
    for (int j = 0; j < 10; j++) {
        uint2 rv = *(const uint2*)(src + j * 4);
        uint2 rw = *(const uint2*)(srco + j * 4);
        float2 v0 = __half22float2(*(__half2*)&rv.x);
        float2 v1 = __half22float2(*(__half2*)&rv.y);
        float2 w0 = __half22float2(*(__half2*)&rw.x);
        float2 w1 = __half22float2(*(__half2*)&rw.y);
        float4 c = *(const float4*)(tc + j * 4);
        float4 s = *(const float4*)(ts + j * 4);
        float o0 = (v0.x * c.x + sgn * w0.x * s.x) * scale;
        float o1 = (v0.y * c.y + sgn * w0.y * s.y) * scale;
        float o2 = (v1.x * c.z + sgn * w1.x * s.z) * scale;
        float o3 = (v1.y * c.w + sgn * w1.y * s.w) * scale;
        *(uint2*)(dst + j * 4) = make_uint2(pack_f16(o0, o1), pack_f16(o2, o3));
    }
}

__global__ __launch_bounds__(128) void attn_f16(
    const __half* __restrict__ qkv, const int* __restrict__ seg,
    const float* __restrict__ rcos, const float* __restrict__ rsin,
    __half* __restrict__ out)
{
    __shared__ __half Qs[64 * AT_STRIDE];
    __shared__ __half Ks[64 * AT_STRIDE];
    __shared__ __half Vs[64 * AT_STRIDE];

    const int head = blockIdx.x;
    const int q0   = blockIdx.y * 64;
    const int tid  = threadIdx.x;
    const int w    = tid >> 5;
    const int lane = tid & 31;
    const int g    = lane >> 2;
    const int t    = lane & 3;

    const float scale = 0.11180339887498949f;

    uint32_t qb, kb, vb;
    asm("{ .reg .u64 u; cvta.to.shared.u64 u, %1; cvt.u32.u64 %0, u; }" : "=r"(qb) : "l"(Qs));
    asm("{ .reg .u64 u; cvta.to.shared.u64 u, %1; cvt.u32.u64 %0, u; }" : "=r"(kb) : "l"(Ks));
    asm("{ .reg .u64 u; cvta.to.shared.u64 u, %1; cvt.u32.u64 %0, u; }" : "=r"(vb) : "l"(Vs));

    const int lrow = tid >> 1;
    const int lh   = tid & 1;
    const float sgn = lh ? 1.f : -1.f;

    {
        const __half* base = qkv + (size_t)(q0 + lrow) * (3 * DMODEL) + head * HDIM;
        load_rope_half_h(base + lh * 40, base + (1 - lh) * 40,
                         rcos + (q0 + lrow) * 40, rsin + (q0 + lrow) * 40,
                         sgn, scale, Qs + lrow * AT_STRIDE + lh * 40);
    }

    float m[2] = {-1e30f, -1e30f};
    float l[2] = {0.f, 0.f};
    float oacc[10][4];
#pragma unroll
    for (int j = 0; j < 10; j++)
#pragma unroll
        for (int i = 0; i < 4; i++) oacc[j][i] = 0.f;

    const int myseg = seg[q0];

    const uint32_t lrow16 = (uint32_t)(lane & 15);
    const uint32_t lhi16  = (uint32_t)(lane >> 4) * 16;
    const uint32_t q_addr0 = qb + (w * 16 + lrow16) * (AT_STRIDE * 2) + lhi16;

    __syncthreads();

    for (int c0 = 0; c0 < S_TOK; c0 += 64) {
        if (seg[c0] != myseg) continue;

        {
            const __half* baseK = qkv + (size_t)(c0 + lrow) * (3 * DMODEL) + DMODEL + head * HDIM;
            load_rope_half_h(baseK + lh * 40, baseK + (1 - lh) * 40,
                             rcos + (c0 + lrow) * 40, rsin + (c0 + lrow) * 40,
                             sgn, 1.f, Ks + lrow * AT_STRIDE + lh * 40);
            const __half* srcV = baseK + DMODEL + lh * 40;
            __half* dV = Vs + lrow * AT_STRIDE + lh * 40;
#pragma unroll
            for (int j = 0; j < 10; j++)
                *(uint2*)(dV + j * 4) = *(const uint2*)(srcV + j * 4);
        }
        __syncthreads();

        float sacc[8][4];
#pragma unroll
        for (int j = 0; j < 8; j++)
#pragma unroll
            for (int i = 0; i < 4; i++) sacc[j][i] = 0.f;

#pragma unroll
        for (int ks = 0; ks < 5; ks++) {
            uint32_t aq[4];
            ldsm4(aq, q_addr0 + ks * 32);
#pragma unroll
            for (int nb = 0; nb < 4; nb++) {
                uint32_t kr[4];
                ldsm4(kr, kb + (nb * 16 + lrow16) * (AT_STRIDE * 2) + lhi16 + ks * 32);
                mma_f16(sacc[2 * nb],     aq[0], aq[1], aq[2], aq[3], kr[0], kr[2]);
                mma_f16(sacc[2 * nb + 1], aq[0], aq[1], aq[2], aq[3], kr[1], kr[3]);
            }
        }

        float cs[2];
#pragma unroll
        for (int i = 0; i < 2; i++) {
            float cm = -1e30f;
#pragma unroll
            for (int j = 0; j < 8; j++) {
                cm = fmaxf(cm, sacc[j][2 * i]);
                cm = fmaxf(cm, sacc[j][2 * i + 1]);
            }
            cm = fmaxf(cm, __shfl_xor_sync(0xffffffffu, cm, 1));
            cm = fmaxf(cm, __shfl_xor_sync(0xffffffffu, cm, 2));
            const float nm = fmaxf(m[i], cm);
            cs[i] = __expf(m[i] - nm);
            m[i] = nm;
            float ps = 0.f;
#pragma unroll
            for (int j = 0; j < 8; j++) {
                float p0 = __expf(sacc[j][2 * i] - nm);
                float p1 = __expf(sacc[j][2 * i + 1] - nm);
                sacc[j][2 * i] = p0; sacc[j][2 * i + 1] = p1;
                ps += p0 + p1;
            }
            ps += __shfl_xor_sync(0xffffffffu, ps, 1);
            ps += __shfl_xor_sync(0xffffffffu, ps, 2);
            l[i] = l[i] * cs[i] + ps;
        }
#pragma unroll
        for (int j = 0; j < 10; j++) {
            oacc[j][0] *= cs[0]; oacc[j][1] *= cs[0];
            oacc[j][2] *= cs[1]; oacc[j][3] *= cs[1];
        }

#pragma unroll
        for (int ks = 0; ks < 4; ks++) {
            uint32_t pp[4];
            pp[0] = pack_f16(sacc[2 * ks][0],     sacc[2 * ks][1]);
            pp[1] = pack_f16(sacc[2 * ks][2],     sacc[2 * ks][3]);
            pp[2] = pack_f16(sacc[2 * ks + 1][0], sacc[2 * ks + 1][1]);
            pp[3] = pack_f16(sacc[2 * ks + 1][2], sacc[2 * ks + 1][3]);
#pragma unroll
            for (int db = 0; db < 5; db++) {
                uint32_t vr[4];
                ldsm4t(vr, vb + (ks * 16 + lrow16) * (AT_STRIDE * 2) + db * 32 + lhi16);
                mma_f16(oacc[2 * db],     pp[0], pp[1], pp[2], pp[3], vr[0], vr[1]);
                mma_f16(oacc[2 * db + 1], pp[0], pp[1], pp[2], pp[3], vr[2], vr[3]);
            }
        }
        __syncthreads();
    }

    const float inv0 = 1.f / l[0];
    const float inv1 = 1.f / l[1];
    const int r0 = q0 + w * 16 + g;
#pragma unroll
    for (int j = 0; j < 10; j++) {
        const int d = head * HDIM + j * 8 + t * 2;
        *(uint32_t*)&out[(size_t)r0 * DMODEL + d] =
            pack_f16(oacc[j][0] * inv0, oacc[j][1] * inv0);
        *(uint32_t*)&out[(size_t)(r0 + 8) * DMODEL + d] =
            pack_f16(oacc[j][2] * inv1, oacc[j][3] * inv1);
    }
}

// ---------------------------------------------------------------------------
// Host side
// ---------------------------------------------------------------------------
static inline void run_gemm(int op, const __half* A, int lda, const __half* B, int ldb,
                            const float* bias, void* C, int M, int N, int K)
{
    dim3 grid(N / 256, (M + 127) / 128);
    switch (op) {
        case 0: gemm_h<0><<<grid, 256, GEMM_SMEM_BYTES>>>(A, lda, B, ldb, bias, C, M, N, K); break;
        case 5: gemm_h<5><<<grid, 256, GEMM_SMEM_BYTES>>>(A, lda, B, ldb, bias, C, M, N, K); break;
        case 6: gemm_h<6><<<grid, 256, GEMM_SMEM_BYTES>>>(A, lda, B, ldb, bias, C, M, N, K); break;
    }
}

static inline void run_splitk(int parts, const __half* A, int ld,
                              const __half* B, float* part_buf,
                              int M, int N, int Kfull)
{
    dim3 grid(N / 256, (M + 127) / 128, parts);
    gemm_h<4><<<grid, 256, GEMM_SMEM_BYTES>>>(A, ld, B, ld, nullptr,
                                              part_buf, M, N, Kfull / parts);
}

extern "C" void kernel_launch(void* const* d_in, const int* in_sizes, int n_in,
                              void* d_out, int out_size)
{
    const float* pixels  = (const float*)d_in[0];
    const float* rotary  = (const float*)d_in[1];
    const int*   seg_ids = (const int*)d_in[2];
    const float* proj_w  = (const float*)d_in[3];
    const float* ln1_w   = (const float*)d_in[4];
    const float* ln1_b   = (const float*)d_in[5];
    const float* qkv_w   = (const float*)d_in[6];
    const float* qkv_b   = (const float*)d_in[7];
    const float* po_w    = (const float*)d_in[8];
    const float* po_b    = (const float*)d_in[9];
    const float* ln2_w   = (const float*)d_in[10];
    const float* ln2_b   = (const float*)d_in[11];
    const float* fc1_w   = (const float*)d_in[12];
    const float* fc1_b   = (const float*)d_in[13];
    const float* fc2_w   = (const float*)d_in[14];
    const float* fc2_b   = (const float*)d_in[15];
    const float* mln_w   = (const float*)d_in[16];
    const float* mln_b   = (const float*)d_in[17];
    const float* m1_w    = (const float*)d_in[18];
    const float* m1_b    = (const float*)d_in[19];
    const float* m2_w    = (const float*)d_in[20];
    const float* m2_b    = (const float*)d_in[21];
    float* out = (float*)d_out;

    float *x, *part, *rcos, *rsin;
    __half *pixh, *projwh, *qkvwh, *powh, *fc1wh, *fc2wh, *m1wh, *m2wh;
    __half *lnh, *qkvh, *atth, *bigh;
    cudaGetSymbolAddress((void**)&x,      g_x);
    cudaGetSymbolAddress((void**)&part,   g_part);
    cudaGetSymbolAddress((void**)&rcos,   g_rcos);
    cudaGetSymbolAddress((void**)&rsin,   g_rsin);
    cudaGetSymbolAddress((void**)&pixh,   g_pix_h);
    cudaGetSymbolAddress((void**)&projwh, g_projw_h);
    cudaGetSymbolAddress((void**)&qkvwh,  g_qkvw_h);
    cudaGetSymbolAddress((void**)&powh,   g_pow_h);
    cudaGetSymbolAddress((void**)&fc1wh,  g_fc1w_h);
    cudaGetSymbolAddress((void**)&fc2wh,  g_fc2w_h);
    cudaGetSymbolAddress((void**)&m1wh,   g_m1w_h);
    cudaGetSymbolAddress((void**)&m2wh,   g_m2w_h);
    cudaGetSymbolAddress((void**)&lnh,    g_ln_h);
    cudaGetSymbolAddress((void**)&qkvh,   g_qkv_h);
    cudaGetSymbolAddress((void**)&atth,   g_att_h);
    cudaGetSymbolAddress((void**)&bigh,   g_big_h);

    cudaFuncSetAttribute(gemm_h<0>, cudaFuncAttributeMaxDynamicSharedMemorySize, GEMM_SMEM_BYTES);
    cudaFuncSetAttribute(gemm_h<4>, cudaFuncAttributeMaxDynamicSharedMemorySize, GEMM_SMEM_BYTES);
    cudaFuncSetAttribute(gemm_h<5>, cudaFuncAttributeMaxDynamicSharedMemorySize, GEMM_SMEM_BYTES);
    cudaFuncSetAttribute(gemm_h<6>, cudaFuncAttributeMaxDynamicSharedMemorySize, GEMM_SMEM_BYTES);

    // weight conversions: one merged kernel for the 6 large unpadded weights
    {
        const long long n_qkv = (long long)DEPTH * 3 * DMODEL * DMODEL / 8;
        const long long n_po  = (long long)DEPTH * DMODEL * DMODEL / 8;
        const long long n_fc1 = (long long)DEPTH * 4 * DMODEL * DMODEL / 8;
        const long long n_fc2 = (long long)DEPTH * DMODEL * 4 * DMODEL / 8;
        const long long n_m1  = (long long)4 * DMODEL * 4 * DMODEL / 8;
        const long long n_m2  = (long long)1536 * 4 * DMODEL / 8;
        const long long e0 = n_qkv;
        const long long e1 = e0 + n_po;
        const long long e2 = e1 + n_fc1;
        const long long e3 = e2 + n_fc2;
        const long long e4 = e3 + n_m1;
        const long long e5 = e4 + n_m2;
        cvt_merged<<<(unsigned)((e5 + 255) / 256), 256>>>(
            qkv_w, qkvwh, e0, po_w, powh, e1, fc1_w, fc1wh, e2,
            fc2_w, fc2wh, e3, m1_w, m1wh, e4, m2_w, m2wh, e5);

        const int tp = S_TOK * KPAD;
        cvt_pad<<<(tp + 255) / 256, 256>>>(pixels, pixh, 1176, KPAD, tp);
        const int tw = DMODEL * KPAD;
        cvt_pad<<<(tw + 255) / 256, 256>>>(proj_w, projwh, 1176, KPAD, tw);
    }
    rope_table<<<(S_TOK * 40 + 255) / 256, 256>>>(rotary, rcos, rsin);

    // patch projection: x = pixels @ proj_w^T (fp32 out)
    run_gemm(0, pixh, KPAD, projwh, KPAD, nullptr, x, S_TOK, DMODEL, KPAD);

    for (int l = 0; l < DEPTH; l++) {
        ln_kernel<<<S_TOK, 256>>>(x, ln1_w + l * DMODEL, ln1_b + l * DMODEL, lnh);
        run_gemm(5, lnh, DMODEL, qkvwh + (size_t)l * 3 * DMODEL * DMODEL, DMODEL,
                 qkv_b + (size_t)l * 3 * DMODEL, qkvh, S_TOK, 3 * DMODEL, DMODEL);
        {
            dim3 grid(NHEAD, S_TOK / 64);
            attn_f16<<<grid, 128>>>(qkvh, seg_ids, rcos, rsin, atth);
        }
        run_splitk(4, atth, DMODEL, powh + (size_t)l * DMODEL * DMODEL, part,
                   S_TOK, DMODEL, DMODEL);
        reduce_k<4, 1><<<(S_TOK * DMODEL / 4 + 255) / 256, 256>>>(
            part, po_b + (size_t)l * DMODEL, x, S_TOK * DMODEL, DMODEL);

        ln_kernel<<<S_TOK, 256>>>(x, ln2_w + l * DMODEL, ln2_b + l * DMODEL, lnh);
        run_gemm(6, lnh, DMODEL, fc1wh + (size_t)l * 4 * DMODEL * DMODEL, DMODEL,
                 fc1_b + (size_t)l * 4 * DMODEL, bigh, S_TOK, 4 * DMODEL, DMODEL);
        run_splitk(4, bigh, 4 * DMODEL,
                   fc2wh + (size_t)l * DMODEL * 4 * DMODEL, part,
                   S_TOK, DMODEL, 4 * DMODEL);
        reduce_k<4, 1><<<(S_TOK * DMODEL / 4 + 255) / 256, 256>>>(
            part, fc2_b + (size_t)l * DMODEL, x, S_TOK * DMODEL, DMODEL);
    }

    ln_kernel<<<S_TOK, 256>>>(x, mln_w, mln_b, lnh);
    run_splitk(4, lnh, 4 * DMODEL, m1wh, part, S_TOK / 4, 4 * DMODEL, 4 * DMODEL);
    reduce_k<4, 4><<<(320 * 4 * DMODEL / 4 + 255) / 256, 256>>>(
        part, m1_b, bigh, 320 * 4 * DMODEL, 4 * DMODEL);
    run_splitk(8, bigh, 4 * DMODEL, m2wh, part, 320, 1536, 4 * DMODEL);
    reduce_k<8, 0><<<(320 * 1536 / 4 + 255) / 256, 256>>>(
        part, m2_b, out, 320 * 1536, 1536);
}

// round 16
// speedup vs baseline: 1.4596x; 1.0178x over previous
#include <cuda_runtime.h>
#include <cuda_bf16.h>
#include <cuda_fp16.h>
#include <math.h>
#include <stdint.h>

// ---------------------------------------------------------------------------
// VisionModel: S=1280, D=1280, H=16, HD=80, DEPTH=4. Output (320,1536) fp32.
// fp16-staged GEMMs (128x256 block, 8 warps x 64x64, BK=32), FA2 attention
// w/ fused RoPE, fused splitK-reduce+LayerNorm.
// ---------------------------------------------------------------------------

#define S_TOK 1280
#define DMODEL 1280
#define NHEAD 16
#define HDIM 80
#define DEPTH 4
#define KPAD 1216   // pixels/proj K padded 1176 -> 1216 (mult of 64 for split2)

// fp16 staging buffers
__device__ __half g_pix_h [S_TOK * KPAD];
__device__ __half g_projw_h[DMODEL * KPAD];
__device__ __half g_qkvw_h[DEPTH * 3 * DMODEL * DMODEL];
__device__ __half g_pow_h [DEPTH * DMODEL * DMODEL];
__device__ __half g_fc1w_h[DEPTH * 4 * DMODEL * DMODEL];
__device__ __half g_fc2w_h[DEPTH * DMODEL * 4 * DMODEL];
__device__ __half g_m1w_h [4 * DMODEL * 4 * DMODEL];
__device__ __half g_m2w_h [1536 * 4 * DMODEL];
__device__ __half g_ln_h  [S_TOK * DMODEL];
__device__ __half g_qkv_h [S_TOK * 3 * DMODEL];
__device__ __half g_att_h [S_TOK * DMODEL];
__device__ __half g_big_h [S_TOK * 4 * DMODEL];
// fp32
__device__ float g_x[S_TOK * DMODEL];
__device__ float g_part[4 * DMODEL * S_TOK];
__device__ float g_rcos[S_TOK * 40];
__device__ float g_rsin[S_TOK * 40];

// ===========================================================================

__device__ __forceinline__ uint32_t pack_f16(float lo, float hi) {
    uint32_t r;
    asm("cvt.rn.f16x2.f32 %0, %1, %2;" : "=r"(r) : "f"(hi), "f"(lo));
    return r;
}

__device__ __forceinline__ void mma_f16(float* c,
    uint32_t a0, uint32_t a1, uint32_t a2, uint32_t a3,
    uint32_t b0, uint32_t b1)
{
    asm volatile(
        "mma.sync.aligned.m16n8k16.row.col.f32.f16.f16.f32 "
        "{%0,%1,%2,%3},{%4,%5,%6,%7},{%8,%9},{%0,%1,%2,%3};"
        : "+f"(c[0]), "+f"(c[1]), "+f"(c[2]), "+f"(c[3])
        : "r"(a0), "r"(a1), "r"(a2), "r"(a3), "r"(b0), "r"(b1));
}

__device__ __forceinline__ int swz(int r) { return ((r ^ (r >> 2)) & 3) << 1; }

// ===========================================================================
// fp16 GEMM (identical core to round-13 winner).
// OP 4: split-K fp32 partial; 5: fp16 out+bias; 6: fp16 SiLU+bias
// ===========================================================================
#define GEMM_SMEM_BYTES ((4128 + 8192) * 4)

template <int OP>
__global__ __launch_bounds__(256) void gemm_h(
    const __half* __restrict__ A, int lda,
    const __half* __restrict__ B, int ldb,
    const float* __restrict__ bias, void* __restrict__ Cv,
    int M, int N, int K)
{
    extern __shared__ uint32_t sm[];

    float* Cf = (float*)Cv;
    __half* Ch = (__half*)Cv;
    if (OP == 4) {
        const size_t zo = (size_t)blockIdx.z * K;
        A += zo; B += zo;
        Cf += (size_t)blockIdx.z * (size_t)M * N;
    }

    const int tid  = threadIdx.x;
    const int warp = tid >> 5;
    const int lane = tid & 31;
    const int g = lane >> 2;
    const int t = lane & 3;

    const int m0 = blockIdx.y * 128;
    const int n0 = blockIdx.x * 256;
    const int warp_m = (warp & 1) * 64;
    const int warp_n = (warp >> 1) * 64;

    const int arow = tid >> 1, asub = tid & 1;
    const bool aok = (m0 + arow) < M;
    const __half* Agp = A + (size_t)(m0 + arow) * lda + asub * 16;
    const __half* Bgp = B + (size_t)(n0 + tid) * ldb;
    const int aswz = swz(arow);
    const int bswz = swz(tid);

    uint32_t* const Aa = sm + asub * 1040 + arow * 8;
    uint32_t* const Bb0 = sm + 4128 + tid * 8;

    float acc[4][8][4];
#pragma unroll
    for (int am = 0; am < 4; am++)
#pragma unroll
        for (int bn = 0; bn < 8; bn++)
#pragma unroll
            for (int i = 0; i < 4; i++) acc[am][bn][i] = 0.f;

    uint4 pA0, pA1, pB00, pB01, pB10, pB11;
    const uint4 z4 = make_uint4(0, 0, 0, 0);

#define LOAD32(k0)                                                             \
    {                                                                          \
        pA0 = aok ? *(const uint4*)(Agp + (k0))     : z4;                      \
        pA1 = aok ? *(const uint4*)(Agp + (k0) + 8) : z4;                      \
        pB00 = *(const uint4*)(Bgp + (k0));                                    \
        pB01 = *(const uint4*)(Bgp + (k0) + 8);                                \
        pB10 = *(const uint4*)(Bgp + (k0) + 16);                               \
        pB11 = *(const uint4*)(Bgp + (k0) + 24);                               \
    }

#define STORE32(buf_)                                                          \
    {                                                                          \
        uint32_t* Ad = Aa + (buf_) * 2064;                                     \
        const uint32_t* a0p = (const uint32_t*)&pA0;                           \
        const uint32_t* a1p = (const uint32_t*)&pA1;                           \
        _Pragma("unroll")                                                      \
        for (int j = 0; j < 4; j++)                                            \
            *(uint2*)&Ad[(2 * j) ^ aswz] = make_uint2(a0p[j], a1p[j]);         \
        uint32_t* Bd0 = Bb0 + (buf_) * 4096;                                   \
        uint32_t* Bd1 = Bd0 + 2048;                                            \
        const uint32_t* b00 = (const uint32_t*)&pB00;                          \
        const uint32_t* b01 = (const uint32_t*)&pB01;                          \
        const uint32_t* b10 = (const uint32_t*)&pB10;                          \
        const uint32_t* b11 = (const uint32_t*)&pB11;                          \
        _Pragma("unroll")                                                      \
        for (int j = 0; j < 4; j++) {                                          \
            *(uint2*)&Bd0[(2 * j) ^ bswz] = make_uint2(b00[j], b01[j]);        \
            *(uint2*)&Bd1[(2 * j) ^ bswz] = make_uint2(b10[j], b11[j]);        \
        }                                                                      \
    }

    LOAD32(0);
    STORE32(0);
    __syncthreads();

    int aoff[4][2], boff[8];
#pragma unroll
    for (int am = 0; am < 4; am++) {
        const int rl = warp_m + am * 16 + g;
        const int rh = rl + 8;
        aoff[am][0] = rl * 8 + ((2 * t) ^ swz(rl));
        aoff[am][1] = rh * 8 + ((2 * t) ^ swz(rh));
    }
#pragma unroll
    for (int bn = 0; bn < 8; bn++) {
        const int rn = warp_n + bn * 8 + g;
        boff[bn] = rn * 8 + ((2 * t) ^ swz(rn));
    }

    const int nstages = K >> 5;
    int buf = 0;

    for (int s = 0; s < nstages; s++) {
        const bool has_next = (s + 1 < nstages);
        if (has_next) LOAD32((s + 1) << 5);

#pragma unroll
        for (int ks2 = 0; ks2 < 2; ks2++) {
            const uint32_t* Ab = sm + buf * 2064 + ks2 * 1040;
            const uint32_t* Bb = sm + 4128 + buf * 4096 + ks2 * 2048;
            uint2 afl[4], afh[4];
#pragma unroll
            for (int am = 0; am < 4; am++) {
                afl[am] = *(const uint2*)&Ab[aoff[am][0]];
                afh[am] = *(const uint2*)&Ab[aoff[am][1]];
            }
            uint2 bf[8];
#pragma unroll
            for (int bn = 0; bn < 8; bn++) bf[bn] = *(const uint2*)&Bb[boff[bn]];

#pragma unroll
            for (int am = 0; am < 4; am++)
#pragma unroll
                for (int bn = 0; bn < 8; bn++)
                    mma_f16(acc[am][bn],
                            afl[am].x, afh[am].x, afl[am].y, afh[am].y,
                            bf[bn].x, bf[bn].y);
        }

        if (has_next) STORE32(buf ^ 1);
        __syncthreads();
        buf ^= 1;
    }
#undef LOAD32
#undef STORE32

#pragma unroll
    for (int am = 0; am < 4; am++) {
        const int r0 = m0 + warp_m + am * 16 + g;
        const int r1 = r0 + 8;
#pragma unroll
        for (int bn = 0; bn < 8; bn++) {
            const int col = n0 + warp_n + bn * 8 + t * 2;
            float2 bb = make_float2(0.f, 0.f);
            if (OP != 4 && bias) bb = *(const float2*)&bias[col];
            const float* cc = acc[am][bn];
#pragma unroll
            for (int half_ = 0; half_ < 2; half_++) {
                const int r = half_ ? r1 : r0;
                if (r >= M) continue;
                float v0 = cc[2 * half_ + 0] + bb.x;
                float v1 = cc[2 * half_ + 1] + bb.y;
                if (OP == 6) {
                    v0 = v0 / (1.f + __expf(-1.702f * v0));
                    v1 = v1 / (1.f + __expf(-1.702f * v1));
                }
                if (OP == 4) {
                    *(float2*)&Cf[(size_t)r * N + col] = make_float2(v0, v1);
                } else {
                    *(uint32_t*)&Ch[(size_t)r * N + col] = pack_f16(v0, v1);
                }
            }
        }
    }
}

// ===========================================================================
// Merged weight conversion (8 elems/thread)
// ===========================================================================
__global__ void cvt_merged(
    const float* __restrict__ s0, __half* __restrict__ d0, long long e0,
    const float* __restrict__ s1, __half* __restrict__ d1, long long e1,
    const float* __restrict__ s2, __half* __restrict__ d2, long long e2,
    const float* __restrict__ s3, __half* __restrict__ d3, long long e3,
    const float* __restrict__ s4, __half* __restrict__ d4, long long e4,
    const float* __restrict__ s5, __half* __restrict__ d5, long long e5)
{
    const long long i = (long long)blockIdx.x * 256 + threadIdx.x;
    if (i >= e5) return;
    const float* s; __half* d; long long base;
    if      (i < e0) { s = s0; d = d0; base = 0;  }
    else if (i < e1) { s = s1; d = d1; base = e0; }
    else if (i < e2) { s = s2; d = d2; base = e1; }
    else if (i < e3) { s = s3; d = d3; base = e2; }
    else if (i < e4) { s = s4; d = d4; base = e3; }
    else             { s = s5; d = d5; base = e4; }
    const long long j = (i - base) * 8;
    const float4 v0 = *(const float4*)(s + j);
    const float4 v1 = *(const float4*)(s + j + 4);
    uint4 o;
    o.x = pack_f16(v0.x, v0.y); o.y = pack_f16(v0.z, v0.w);
    o.z = pack_f16(v1.x, v1.y); o.w = pack_f16(v1.z, v1.w);
    *(uint4*)(d + j) = o;
}

__global__ void cvt_pad(const float* __restrict__ src, __half* __restrict__ dst,
                        int cols, int colsPad, int total)
{
    const int i = blockIdx.x * 256 + threadIdx.x;
    if (i >= total) return;
    const int r = i / colsPad, c = i % colsPad;
    dst[i] = (c < cols) ? __float2half(src[(size_t)r * cols + c]) : __half(0.f);
}

// ===========================================================================
// Fused split-K reduce + residual + LayerNorm.
// One block per row (320 threads x float4 over 1280 cols).
// SET=1: x = sum(+bias); SET=0: x += sum+bias. Then lnh = LN(x)*w+b (fp16).
// ===========================================================================
template <int NP, int SET>
__global__ __launch_bounds__(320) void reduce_ln(
    const float* __restrict__ part, const float* __restrict__ bias,
    float* __restrict__ x, const float* __restrict__ lw,
    const float* __restrict__ lb, __half* __restrict__ y)
{
    const int row = blockIdx.x;
    const int tid = threadIdx.x;
    const int col = tid * 4;
    const int idx = row * DMODEL + col;
    const int TOT = S_TOK * DMODEL;

    float4 s = bias ? *(const float4*)&bias[col] : make_float4(0.f, 0.f, 0.f, 0.f);
#pragma unroll
    for (int c = 0; c < NP; c++) {
        const float4 p = *(const float4*)&part[(size_t)c * TOT + idx];
        s.x += p.x; s.y += p.y; s.z += p.z; s.w += p.w;
    }
    float4 xv;
    if (SET) {
        xv = s;
    } else {
        xv = *(const float4*)&x[idx];
        xv.x += s.x; xv.y += s.y; xv.z += s.z; xv.w += s.w;
    }
    *(float4*)&x[idx] = xv;

    float sum = xv.x + xv.y + xv.z + xv.w;
    float sq  = xv.x * xv.x + xv.y * xv.y + xv.z * xv.z + xv.w * xv.w;
#pragma unroll
    for (int o = 16; o > 0; o >>= 1) {
        sum += __shfl_xor_sync(0xffffffffu, sum, o);
        sq  += __shfl_xor_sync(0xffffffffu, sq, o);
    }
    __shared__ float ws[10], wsq[10];
    if ((tid & 31) == 0) { ws[tid >> 5] = sum; wsq[tid >> 5] = sq; }
    __syncthreads();
    __shared__ float s_mu, s_rstd;
    if (tid == 0) {
        float ts = 0.f, tsq = 0.f;
#pragma unroll
        for (int i = 0; i < 10; i++) { ts += ws[i]; tsq += wsq[i]; }
        const float mu = ts / DMODEL;
        const float var = tsq / DMODEL - mu * mu;
        s_mu = mu;
        s_rstd = rsqrtf(var + 1e-6f);
    }
    __syncthreads();
    const float mu = s_mu, rstd = s_rstd;
    const float4 w4 = *(const float4*)&lw[col];
    const float4 b4 = *(const float4*)&lb[col];
    const float o0 = (xv.x - mu) * rstd * w4.x + b4.x;
    const float o1 = (xv.y - mu) * rstd * w4.y + b4.y;
    const float o2 = (xv.z - mu) * rstd * w4.z + b4.z;
    const float o3 = (xv.w - mu) * rstd * w4.w + b4.w;
    *(uint2*)&y[idx] = make_uint2(pack_f16(o0, o1), pack_f16(o2, o3));
}

// ===========================================================================
// split-K reduce (m1/m2 only), 4 elems/thread.
// MODE 0: f32 = sum+bias; 4: f16 GELU(sum+bias)
// ===========================================================================
template <int NP, int MODE>
__global__ void reduce_k(const float* __restrict__ part,
                         const float* __restrict__ bias,
                         void* __restrict__ dstv, int total, int ncols)
{
    const int i = blockIdx.x * 256 + threadIdx.x;
    const int idx = i * 4;
    if (idx >= total) return;
    float4 s = *(const float4*)&bias[idx % ncols];
#pragma unroll
    for (int c = 0; c < NP; c++) {
        const float4 p = *(const float4*)&part[(size_t)c * total + idx];
        s.x += p.x; s.y += p.y; s.z += p.z; s.w += p.w;
    }
    if (MODE == 0) {
        *(float4*)&((float*)dstv)[idx] = s;
    } else {
        const float g0 = 0.5f * s.x * (1.f + erff(s.x * 0.7071067811865475f));
        const float g1 = 0.5f * s.y * (1.f + erff(s.y * 0.7071067811865475f));
        const float g2 = 0.5f * s.z * (1.f + erff(s.z * 0.7071067811865475f));
        const float g3 = 0.5f * s.w * (1.f + erff(s.w * 0.7071067811865475f));
        *(uint2*)&((__half*)dstv)[idx] =
            make_uint2(pack_f16(g0, g1), pack_f16(g2, g3));
    }
}

// ---------------------------------------------------------------------------
// RoPE cos/sin tables
// ---------------------------------------------------------------------------
__global__ void rope_table(const float* __restrict__ rotary,
                           float* __restrict__ rcos, float* __restrict__ rsin)
{
    const int i = blockIdx.x * 256 + threadIdx.x;
    if (i >= S_TOK * 40) return;
    float c, s;
    sincosf(rotary[i], &s, &c);
    rcos[i] = c;
    rsin[i] = s;
}

// ===========================================================================
// Attention: FA2-style fp16 mma (fp32 accum), 128 thr = 4 warps, fused RoPE.
// ===========================================================================
#define AT_STRIDE 88

__device__ __forceinline__ void ldsm4(uint32_t* r, uint32_t addr) {
    asm volatile("ldmatrix.sync.aligned.m8n8.x4.shared.b16 {%0,%1,%2,%3}, [%4];"
                 : "=r"(r[0]), "=r"(r[1]), "=r"(r[2]), "=r"(r[3]) : "r"(addr));
}
__device__ __forceinline__ void ldsm4t(uint32_t* r, uint32_t addr) {
    asm volatile("ldmatrix.sync.aligned.m8n8.x4.trans.shared.b16 {%0,%1,%2,%3}, [%4];"
                 : "=r"(r[0]), "=r"(r[1]), "=r"(r[2]), "=r"(r[3]) : "r"(addr));
}

__device__ __forceinline__ void load_rope_half_h(
    const __half* __restrict__ src, const __half* __restrict__ srco,
    const float* __restrict__ tc, const float* __restrict__ ts,
    float sgn, float scale, __half* dst)
{
#pragma unroll
    for (int j = 0; j < 10; j++) {
        uint2 rv = *(const uint2*)(src + j * 4);
        uint2 rw = *(const uint2*)(srco + j * 4);
        float2 v0 = __half22float2(*(__half2*)&rv.x);
        float2 v1 = __half22float2(*(__half2*)&rv.y);
        float2 w0 = __half22float2(*(__half2*)&rw.x);
        float2 w1 = __half22float2(*(__half2*)&rw.y);
        float4 c = *(const float4*)(tc + j * 4);
        float4 s = *(const float4*)(ts + j * 4);
        float o0 = (v0.x * c.x + sgn * w0.x * s.x) * scale;
        float o1 = (v0.y * c.y + sgn * w0.y * s.y) * scale;
        float o2 = (v1.x * c.z + sgn * w1.x * s.z) * scale;
        float o3 = (v1.y * c.w + sgn * w1.y * s.w) * scale;
        *(uint2*)(dst + j * 4) = make_uint2(pack_f16(o0, o1), pack_f16(o2, o3));
    }
}

__global__ __launch_bounds__(128) void attn_f16(
    const __half* __restrict__ qkv, const int* __restrict__ seg,
    const float* __restrict__ rcos, const float* __restrict__ rsin,
    __half* __restrict__ out)
{
    __shared__ __half Qs[64 * AT_STRIDE];
    __shared__ __half Ks[64 * AT_STRIDE];
    __shared__ __half Vs[64 * AT_STRIDE];

    const int head = blockIdx.x;
    const int q0   = blockIdx.y * 64;
    const int tid  = threadIdx.x;
    const int w    = tid >> 5;
    const int lane = tid & 31;
    const int g    = lane >> 2;
    const int t    = lane & 3;

    const float scale = 0.11180339887498949f;

    uint32_t qb, kb, vb;
    asm("{ .reg .u64 u; cvta.to.shared.u64 u, %1; cvt.u32.u64 %0, u; }" : "=r"(qb) : "l"(Qs));
    asm("{ .reg .u64 u; cvta.to.shared.u64 u, %1; cvt.u32.u64 %0, u; }" : "=r"(kb) : "l"(Ks));
    asm("{ .reg .u64 u; cvta.to.shared.u64 u, %1; cvt.u32.u64 %0, u; }" : "=r"(vb) : "l"(Vs));

    const int lrow = tid >> 1;
    const int lh   = tid & 1;
    const float sgn = lh ? 1.f : -1.f;

    {
        const __half* base = qkv + (size_t)(q0 + lrow) * (3 * DMODEL) + head * HDIM;
        load_rope_half_h(base + lh * 40, base + (1 - lh) * 40,
                         rcos + (q0 + lrow) * 40, rsin + (q0 + lrow) * 40,
                         sgn, scale, Qs + lrow * AT_STRIDE + lh * 40);
    }

    float m[2] = {-1e30f, -1e30f};
    float l[2] = {0.f, 0.f};
    float oacc[10][4];
#pragma unroll
    for (int j = 0; j < 10; j++)
#pragma unroll
        for (int i = 0; i < 4; i++) oacc[j][i] = 0.f;

    const int myseg = seg[q0];

    const uint32_t lrow16 = (uint32_t)(lane & 15);
    const uint32_t lhi16  = (uint32_t)(lane >> 4) * 16;
    const uint32_t q_addr0 = qb + (w * 16 + lrow16) * (AT_STRIDE * 2) + lhi16;

    __syncthreads();

    for (int c0 = 0; c0 < S_TOK; c0 += 64) {
        if (seg[c0] != myseg) continue;

        {
            const __half* baseK = qkv + (size_t)(c0 + lrow) * (3 * DMODEL) + DMODEL + head * HDIM;
            load_rope_half_h(baseK + lh * 40, baseK + (1 - lh) * 40,
                             rcos + (c0 + lrow) * 40, rsin + (c0 + lrow) * 40,
                             sgn, 1.f, Ks + lrow * AT_STRIDE + lh * 40);
            const __half* srcV = baseK + DMODEL + lh * 40;
            __half* dV = Vs + lrow * AT_STRIDE + lh * 40;
#pragma unroll
            for (int j = 0; j < 10; j++)
                *(uint2*)(dV + j * 4) = *(const uint2*)(srcV + j * 4);
        }
        __syncthreads();

        float sacc[8][4];
#pragma unroll
        for (int j = 0; j < 8; j++)
#pragma unroll
            for (int i = 0; i < 4; i++) sacc[j][i] = 0.f;

#pragma unroll
        for (int ks = 0; ks < 5; ks++) {
            uint32_t aq[4];
            ldsm4(aq, q_addr0 + ks * 32);
#pragma unroll
            for (int nb = 0; nb < 4; nb++) {
                uint32_t kr[4];
                ldsm4(kr, kb + (nb * 16 + lrow16) * (AT_STRIDE * 2) + lhi16 + ks * 32);
                mma_f16(sacc[2 * nb],     aq[0], aq[1], aq[2], aq[3], kr[0], kr[2]);
                mma_f16(sacc[2 * nb + 1], aq[0], aq[1], aq[2], aq[3], kr[1], kr[3]);
            }
        }

        float cs[2];
#pragma unroll
        for (int i = 0; i < 2; i++) {
            float cm = -1e30f;
#pragma unroll
            for (int j = 0; j < 8; j++) {
                cm = fmaxf(cm, sacc[j][2 * i]);
                cm = fmaxf(cm, sacc[j][2 * i + 1]);
            }
            cm = fmaxf(cm, __shfl_xor_sync(0xffffffffu, cm, 1));
            cm = fmaxf(cm, __shfl_xor_sync(0xffffffffu, cm, 2));
            const float nm = fmaxf(m[i], cm);
            cs[i] = __expf(m[i] - nm);
            m[i] = nm;
            float ps = 0.f;
#pragma unroll
            for (int j = 0; j < 8; j++) {
                float p0 = __expf(sacc[j][2 * i] - nm);
                float p1 = __expf(sacc[j][2 * i + 1] - nm);
                sacc[j][2 * i] = p0; sacc[j][2 * i + 1] = p1;
                ps += p0 + p1;
            }
            ps += __shfl_xor_sync(0xffffffffu, ps, 1);
            ps += __shfl_xor_sync(0xffffffffu, ps, 2);
            l[i] = l[i] * cs[i] + ps;
        }
#pragma unroll
        for (int j = 0; j < 10; j++) {
            oacc[j][0] *= cs[0]; oacc[j][1] *= cs[0];
            oacc[j][2] *= cs[1]; oacc[j][3] *= cs[1];
        }

#pragma unroll
        for (int ks = 0; ks < 4; ks++) {
            uint32_t pp[4];
            pp[0] = pack_f16(sacc[2 * ks][0],     sacc[2 * ks][1]);
            pp[1] = pack_f16(sacc[2 * ks][2],     sacc[2 * ks][3]);
            pp[2] = pack_f16(sacc[2 * ks + 1][0], sacc[2 * ks + 1][1]);
            pp[3] = pack_f16(sacc[2 * ks + 1][2], sacc[2 * ks + 1][3]);
#pragma unroll
            for (int db = 0; db < 5; db++) {
                uint32_t vr[4];
                ldsm4t(vr, vb + (ks * 16 + lrow16) * (AT_STRIDE * 2) + db * 32 + lhi16);
                mma_f16(oacc[2 * db],     pp[0], pp[1], pp[2], pp[3], vr[0], vr[1]);
                mma_f16(oacc[2 * db + 1], pp[0], pp[1], pp[2], pp[3], vr[2], vr[3]);
            }
        }
        __syncthreads();
    }

    const float inv0 = 1.f / l[0];
    const float inv1 = 1.f / l[1];
    const int r0 = q0 + w * 16 + g;
#pragma unroll
    for (int j = 0; j < 10; j++) {
        const int d = head * HDIM + j * 8 + t * 2;
        *(uint32_t*)&out[(size_t)r0 * DMODEL + d] =
            pack_f16(oacc[j][0] * inv0, oacc[j][1] * inv0);
        *(uint32_t*)&out[(size_t)(r0 + 8) * DMODEL + d] =
            pack_f16(oacc[j][2] * inv1, oacc[j][3] * inv1);
    }
}

// ---------------------------------------------------------------------------
// Host side
// ---------------------------------------------------------------------------
static inline void run_gemm(int op, const __half* A, int lda, const __half* B, int ldb,
                            const float* bias, void* C, int M, int N, int K)
{
    dim3 grid(N / 256, (M + 127) / 128);
    switch (op) {
        case 5: gemm_h<5><<<grid, 256, GEMM_SMEM_BYTES>>>(A, lda, B, ldb, bias, C, M, N, K); break;
        case 6: gemm_h<6><<<grid, 256, GEMM_SMEM_BYTES>>>(A, lda, B, ldb, bias, C, M, N, K); break;
    }
}

static inline void run_splitk(int parts, const __half* A, int ld,
                              const __half* B, float* part_buf,
                              int M, int N, int Kfull)
{
    dim3 grid(N / 256, (M + 127) / 128, parts);
    gemm_h<4><<<grid, 256, GEMM_SMEM_BYTES>>>(A, ld, B, ld, nullptr,
                                              part_buf, M, N, Kfull / parts);
}

extern "C" void kernel_launch(void* const* d_in, const int* in_sizes, int n_in,
                              void* d_out, int out_size)
{
    const float* pixels  = (const float*)d_in[0];
    const float* rotary  = (const float*)d_in[1];
    const int*   seg_ids = (const int*)d_in[2];
    const float* proj_w  = (const float*)d_in[3];
    const float* ln1_w   = (const float*)d_in[4];
    const float* ln1_b   = (const float*)d_in[5];
    const float* qkv_w   = (const float*)d_in[6];
    const float* qkv_b   = (const float*)d_in[7];
    const float* po_w    = (const float*)d_in[8];
    const float* po_b    = (const float*)d_in[9];
    const float* ln2_w   = (const float*)d_in[10];
    const float* ln2_b   = (const float*)d_in[11];
    const float* fc1_w   = (const float*)d_in[12];
    const float* fc1_b   = (const float*)d_in[13];
    const float* fc2_w   = (const float*)d_in[14];
    const float* fc2_b   = (const float*)d_in[15];
    const float* mln_w   = (const float*)d_in[16];
    const float* mln_b   = (const float*)d_in[17];
    const float* m1_w    = (const float*)d_in[18];
    const float* m1_b    = (const float*)d_in[19];
    const float* m2_w    = (const float*)d_in[20];
    const float* m2_b    = (const float*)d_in[21];
    float* out = (float*)d_out;

    float *x, *part, *rcos, *rsin;
    __half *pixh, *projwh, *qkvwh, *powh, *fc1wh, *fc2wh, *m1wh, *m2wh;
    __half *lnh, *qkvh, *atth, *bigh;
    cudaGetSymbolAddress((void**)&x,      g_x);
    cudaGetSymbolAddress((void**)&part,   g_part);
    cudaGetSymbolAddress((void**)&rcos,   g_rcos);
    cudaGetSymbolAddress((void**)&rsin,   g_rsin);
    cudaGetSymbolAddress((void**)&pixh,   g_pix_h);
    cudaGetSymbolAddress((void**)&projwh, g_projw_h);
    cudaGetSymbolAddress((void**)&qkvwh,  g_qkvw_h);
    cudaGetSymbolAddress((void**)&powh,   g_pow_h);
    cudaGetSymbolAddress((void**)&fc1wh,  g_fc1w_h);
    cudaGetSymbolAddress((void**)&fc2wh,  g_fc2w_h);
    cudaGetSymbolAddress((void**)&m1wh,   g_m1w_h);
    cudaGetSymbolAddress((void**)&m2wh,   g_m2w_h);
    cudaGetSymbolAddress((void**)&lnh,    g_ln_h);
    cudaGetSymbolAddress((void**)&qkvh,   g_qkv_h);
    cudaGetSymbolAddress((void**)&atth,   g_att_h);
    cudaGetSymbolAddress((void**)&bigh,   g_big_h);

    cudaFuncSetAttribute(gemm_h<4>, cudaFuncAttributeMaxDynamicSharedMemorySize, GEMM_SMEM_BYTES);
    cudaFuncSetAttribute(gemm_h<5>, cudaFuncAttributeMaxDynamicSharedMemorySize, GEMM_SMEM_BYTES);
    cudaFuncSetAttribute(gemm_h<6>, cudaFuncAttributeMaxDynamicSharedMemorySize, GEMM_SMEM_BYTES);

    // weight conversions
    {
        const long long n_qkv = (long long)DEPTH * 3 * DMODEL * DMODEL / 8;
        const long long n_po  = (long long)DEPTH * DMODEL * DMODEL / 8;
        const long long n_fc1 = (long long)DEPTH * 4 * DMODEL * DMODEL / 8;
        const long long n_fc2 = (long long)DEPTH * DMODEL * 4 * DMODEL / 8;
        const long long n_m1  = (long long)4 * DMODEL * 4 * DMODEL / 8;
        const long long n_m2  = (long long)1536 * 4 * DMODEL / 8;
        const long long e0 = n_qkv;
        const long long e1 = e0 + n_po;
        const long long e2 = e1 + n_fc1;
        const long long e3 = e2 + n_fc2;
        const long long e4 = e3 + n_m1;
        const long long e5 = e4 + n_m2;
        cvt_merged<<<(unsigned)((e5 + 255) / 256), 256>>>(
            qkv_w, qkvwh, e0, po_w, powh, e1, fc1_w, fc1wh, e2,
            fc2_w, fc2wh, e3, m1_w, m1wh, e4, m2_w, m2wh, e5);

        const int tp = S_TOK * KPAD;
        cvt_pad<<<(tp + 255) / 256, 256>>>(pixels, pixh, 1176, KPAD, tp);
        const int tw = DMODEL * KPAD;
        cvt_pad<<<(tw + 255) / 256, 256>>>(proj_w, projwh, 1176, KPAD, tw);
    }
    rope_table<<<(S_TOK * 40 + 255) / 256, 256>>>(rotary, rcos, rsin);

    // proj: split-K x2 -> fused reduce (x = sum) + LN1(layer0) -> lnh
    run_splitk(2, pixh, KPAD, projwh, part, S_TOK, DMODEL, KPAD);
    reduce_ln<2, 1><<<S_TOK, 320>>>(part, nullptr, x, ln1_w, ln1_b, lnh);

    for (int l = 0; l < DEPTH; l++) {
        run_gemm(5, lnh, DMODEL, qkvwh + (size_t)l * 3 * DMODEL * DMODEL, DMODEL,
                 qkv_b + (size_t)l * 3 * DMODEL, qkvh, S_TOK, 3 * DMODEL, DMODEL);
        {
            dim3 grid(NHEAD, S_TOK / 64);
            attn_f16<<<grid, 128>>>(qkvh, seg_ids, rcos, rsin, atth);
        }
        // po: split-K x4 -> fused (x += sum+bias) + LN2 -> lnh
        run_splitk(4, atth, DMODEL, powh + (size_t)l * DMODEL * DMODEL, part,
                   S_TOK, DMODEL, DMODEL);
        reduce_ln<4, 0><<<S_TOK, 320>>>(part, po_b + (size_t)l * DMODEL, x,
                                        ln2_w + l * DMODEL, ln2_b + l * DMODEL, lnh);

        run_gemm(6, lnh, DMODEL, fc1wh + (size_t)l * 4 * DMODEL * DMODEL, DMODEL,
                 fc1_b + (size_t)l * 4 * DMODEL, bigh, S_TOK, 4 * DMODEL, DMODEL);
        // fc2: split-K x4 -> fused (x += sum+bias) + next LN (ln1[l+1] or mln)
        run_splitk(4, bigh, 4 * DMODEL,
                   fc2wh + (size_t)l * DMODEL * 4 * DMODEL, part,
                   S_TOK, DMODEL, 4 * DMODEL);
        const float* nw = (l + 1 < DEPTH) ? ln1_w + (l + 1) * DMODEL : mln_w;
        const float* nb = (l + 1 < DEPTH) ? ln1_b + (l + 1) * DMODEL : mln_b;
        reduce_ln<4, 0><<<S_TOK, 320>>>(part, fc2_b + (size_t)l * DMODEL, x,
                                        nw, nb, lnh);
    }

    // m1: split-K x4, GELU->fp16 in reduce -> bigh
    run_splitk(4, lnh, 4 * DMODEL, m1wh, part, S_TOK / 4, 4 * DMODEL, 4 * DMODEL);
    reduce_k<4, 4><<<(320 * 4 * DMODEL / 4 + 255) / 256, 256>>>(
        part, m1_b, bigh, 320 * 4 * DMODEL, 4 * DMODEL);
    // m2: split-K x8 -> reduce -> out (fp32)
    run_splitk(8, bigh, 4 * DMODEL, m2wh, part, 320, 1536, 4 * DMODEL);
    reduce_k<8, 0><<<(320 * 1536 / 4 + 255) / 256, 256>>>(
        part, m2_b, out, 320 * 1536, 1536);
}

// round 17
// speedup vs baseline: 1.6159x; 1.1071x over previous
#include <cuda_runtime.h>
#include <cuda_bf16.h>
#include <cuda_fp16.h>
#include <math.h>
#include <stdint.h>

// ---------------------------------------------------------------------------
// VisionModel: S=1280, D=1280, H=16, HD=80, DEPTH=4. Output (320,1536) fp32.
// fp16-staged GEMMs (128x256 block, 8 warps x 64x64, BK=32), wave-shaped
// split-K everywhere, FA2 attention w/ fused RoPE, fused reduce+LN.
// ---------------------------------------------------------------------------

#define S_TOK 1280
#define DMODEL 1280
#define NHEAD 16
#define HDIM 80
#define DEPTH 4
#define KPAD 1216

// fp16 staging buffers
__device__ __half g_pix_h [S_TOK * KPAD];
__device__ __half g_projw_h[DMODEL * KPAD];
__device__ __half g_qkvw_h[DEPTH * 3 * DMODEL * DMODEL];
__device__ __half g_pow_h [DEPTH * DMODEL * DMODEL];
__device__ __half g_fc1w_h[DEPTH * 4 * DMODEL * DMODEL];
__device__ __half g_fc2w_h[DEPTH * DMODEL * 4 * DMODEL];
__device__ __half g_m1w_h [4 * DMODEL * 4 * DMODEL];
__device__ __half g_m2w_h [1536 * 4 * DMODEL];
__device__ __half g_ln_h  [S_TOK * DMODEL];
__device__ __half g_qkv_h [S_TOK * 3 * DMODEL];
__device__ __half g_att_h [S_TOK * DMODEL];
__device__ __half g_big_h [S_TOK * 4 * DMODEL];
// fp32
__device__ float g_x[S_TOK * DMODEL];
__device__ float g_part[8 * DMODEL * S_TOK + 4 * S_TOK * DMODEL];  // 13.1M floats
__device__ float g_rcos[S_TOK * 40];
__device__ float g_rsin[S_TOK * 40];

// ===========================================================================

__device__ __forceinline__ uint32_t pack_f16(float lo, float hi) {
    uint32_t r;
    asm("cvt.rn.f16x2.f32 %0, %1, %2;" : "=r"(r) : "f"(hi), "f"(lo));
    return r;
}

__device__ __forceinline__ void mma_f16(float* c,
    uint32_t a0, uint32_t a1, uint32_t a2, uint32_t a3,
    uint32_t b0, uint32_t b1)
{
    asm volatile(
        "mma.sync.aligned.m16n8k16.row.col.f32.f16.f16.f32 "
        "{%0,%1,%2,%3},{%4,%5,%6,%7},{%8,%9},{%0,%1,%2,%3};"
        : "+f"(c[0]), "+f"(c[1]), "+f"(c[2]), "+f"(c[3])
        : "r"(a0), "r"(a1), "r"(a2), "r"(a3), "r"(b0), "r"(b1));
}

__device__ __forceinline__ int swz(int r) { return ((r ^ (r >> 2)) & 3) << 1; }

// ===========================================================================
// fp16 GEMM (identical core). OP 4: split-K fp32 partial;
// 5: fp16 out+bias; 6: fp16 SiLU+bias
// ===========================================================================
#define GEMM_SMEM_BYTES ((4128 + 8192) * 4)

template <int OP>
__global__ __launch_bounds__(256) void gemm_h(
    const __half* __restrict__ A, int lda,
    const __half* __restrict__ B, int ldb,
    const float* __restrict__ bias, void* __restrict__ Cv,
    int M, int N, int K)
{
    extern __shared__ uint32_t sm[];

    float* Cf = (float*)Cv;
    __half* Ch = (__half*)Cv;
    if (OP == 4) {
        const size_t zo = (size_t)blockIdx.z * K;
        A += zo; B += zo;
        Cf += (size_t)blockIdx.z * (size_t)M * N;
    }

    const int tid  = threadIdx.x;
    const int warp = tid >> 5;
    const int lane = tid & 31;
    const int g = lane >> 2;
    const int t = lane & 3;

    const int m0 = blockIdx.y * 128;
    const int n0 = blockIdx.x * 256;
    const int warp_m = (warp & 1) * 64;
    const int warp_n = (warp >> 1) * 64;

    const int arow = tid >> 1, asub = tid & 1;
    const bool aok = (m0 + arow) < M;
    const __half* Agp = A + (size_t)(m0 + arow) * lda + asub * 16;
    const __half* Bgp = B + (size_t)(n0 + tid) * ldb;
    const int aswz = swz(arow);
    const int bswz = swz(tid);

    uint32_t* const Aa = sm + asub * 1040 + arow * 8;
    uint32_t* const Bb0 = sm + 4128 + tid * 8;

    float acc[4][8][4];
#pragma unroll
    for (int am = 0; am < 4; am++)
#pragma unroll
        for (int bn = 0; bn < 8; bn++)
#pragma unroll
            for (int i = 0; i < 4; i++) acc[am][bn][i] = 0.f;

    uint4 pA0, pA1, pB00, pB01, pB10, pB11;
    const uint4 z4 = make_uint4(0, 0, 0, 0);

#define LOAD32(k0)                                                             \
    {                                                                          \
        pA0 = aok ? *(const uint4*)(Agp + (k0))     : z4;                      \
        pA1 = aok ? *(const uint4*)(Agp + (k0) + 8) : z4;                      \
        pB00 = *(const uint4*)(Bgp + (k0));                                    \
        pB01 = *(const uint4*)(Bgp + (k0) + 8);                                \
        pB10 = *(const uint4*)(Bgp + (k0) + 16);                               \
        pB11 = *(const uint4*)(Bgp + (k0) + 24);                               \
    }

#define STORE32(buf_)                                                          \
    {                                                                          \
        uint32_t* Ad = Aa + (buf_) * 2064;                                     \
        const uint32_t* a0p = (const uint32_t*)&pA0;                           \
        const uint32_t* a1p = (const uint32_t*)&pA1;                           \
        _Pragma("unroll")                                                      \
        for (int j = 0; j < 4; j++)                                            \
            *(uint2*)&Ad[(2 * j) ^ aswz] = make_uint2(a0p[j], a1p[j]);         \
        uint32_t* Bd0 = Bb0 + (buf_) * 4096;                                   \
        uint32_t* Bd1 = Bd0 + 2048;                                            \
        const uint32_t* b00 = (const uint32_t*)&pB00;                          \
        const uint32_t* b01 = (const uint32_t*)&pB01;                          \
        const uint32_t* b10 = (const uint32_t*)&pB10;                          \
        const uint32_t* b11 = (const uint32_t*)&pB11;                          \
        _Pragma("unroll")                                                      \
        for (int j = 0; j < 4; j++) {                                          \
            *(uint2*)&Bd0[(2 * j) ^ bswz] = make_uint2(b00[j], b01[j]);        \
            *(uint2*)&Bd1[(2 * j) ^ bswz] = make_uint2(b10[j], b11[j]);        \
        }                                                                      \
    }

    LOAD32(0);
    STORE32(0);
    __syncthreads();

    int aoff[4][2], boff[8];
#pragma unroll
    for (int am = 0; am < 4; am++) {
        const int rl = warp_m + am * 16 + g;
        const int rh = rl + 8;
        aoff[am][0] = rl * 8 + ((2 * t) ^ swz(rl));
        aoff[am][1] = rh * 8 + ((2 * t) ^ swz(rh));
    }
#pragma unroll
    for (int bn = 0; bn < 8; bn++) {
        const int rn = warp_n + bn * 8 + g;
        boff[bn] = rn * 8 + ((2 * t) ^ swz(rn));
    }

    const int nstages = K >> 5;
    int buf = 0;

    for (int s = 0; s < nstages; s++) {
        const bool has_next = (s + 1 < nstages);
        if (has_next) LOAD32((s + 1) << 5);

#pragma unroll
        for (int ks2 = 0; ks2 < 2; ks2++) {
            const uint32_t* Ab = sm + buf * 2064 + ks2 * 1040;
            const uint32_t* Bb = sm + 4128 + buf * 4096 + ks2 * 2048;
            uint2 afl[4], afh[4];
#pragma unroll
            for (int am = 0; am < 4; am++) {
                afl[am] = *(const uint2*)&Ab[aoff[am][0]];
                afh[am] = *(const uint2*)&Ab[aoff[am][1]];
            }
            uint2 bf[8];
#pragma unroll
            for (int bn = 0; bn < 8; bn++) bf[bn] = *(const uint2*)&Bb[boff[bn]];

#pragma unroll
            for (int am = 0; am < 4; am++)
#pragma unroll
                for (int bn = 0; bn < 8; bn++)
                    mma_f16(acc[am][bn],
                            afl[am].x, afh[am].x, afl[am].y, afh[am].y,
                            bf[bn].x, bf[bn].y);
        }

        if (has_next) STORE32(buf ^ 1);
        __syncthreads();
        buf ^= 1;
    }
#undef LOAD32
#undef STORE32

#pragma unroll
    for (int am = 0; am < 4; am++) {
        const int r0 = m0 + warp_m + am * 16 + g;
        const int r1 = r0 + 8;
#pragma unroll
        for (int bn = 0; bn < 8; bn++) {
            const int col = n0 + warp_n + bn * 8 + t * 2;
            float2 bb = make_float2(0.f, 0.f);
            if (OP != 4 && bias) bb = *(const float2*)&bias[col];
            const float* cc = acc[am][bn];
#pragma unroll
            for (int half_ = 0; half_ < 2; half_++) {
                const int r = half_ ? r1 : r0;
                if (r >= M) continue;
                float v0 = cc[2 * half_ + 0] + bb.x;
                float v1 = cc[2 * half_ + 1] + bb.y;
                if (OP == 6) {
                    v0 = v0 / (1.f + __expf(-1.702f * v0));
                    v1 = v1 / (1.f + __expf(-1.702f * v1));
                }
                if (OP == 4) {
                    *(float2*)&Cf[(size_t)r * N + col] = make_float2(v0, v1);
                } else {
                    *(uint32_t*)&Ch[(size_t)r * N + col] = pack_f16(v0, v1);
                }
            }
        }
    }
}

// ===========================================================================
// Merged weight conversion (8 elems/thread)
// ===========================================================================
__global__ void cvt_merged(
    const float* __restrict__ s0, __half* __restrict__ d0, long long e0,
    const float* __restrict__ s1, __half* __restrict__ d1, long long e1,
    const float* __restrict__ s2, __half* __restrict__ d2, long long e2,
    const float* __restrict__ s3, __half* __restrict__ d3, long long e3,
    const float* __restrict__ s4, __half* __restrict__ d4, long long e4,
    const float* __restrict__ s5, __half* __restrict__ d5, long long e5)
{
    const long long i = (long long)blockIdx.x * 256 + threadIdx.x;
    if (i >= e5) return;
    const float* s; __half* d; long long base;
    if      (i < e0) { s = s0; d = d0; base = 0;  }
    else if (i < e1) { s = s1; d = d1; base = e0; }
    else if (i < e2) { s = s2; d = d2; base = e1; }
    else if (i < e3) { s = s3; d = d3; base = e2; }
    else if (i < e4) { s = s4; d = d4; base = e3; }
    else             { s = s5; d = d5; base = e4; }
    const long long j = (i - base) * 8;
    const float4 v0 = *(const float4*)(s + j);
    const float4 v1 = *(const float4*)(s + j + 4);
    uint4 o;
    o.x = pack_f16(v0.x, v0.y); o.y = pack_f16(v0.z, v0.w);
    o.z = pack_f16(v1.x, v1.y); o.w = pack_f16(v1.z, v1.w);
    *(uint4*)(d + j) = o;
}

__global__ void cvt_pad(const float* __restrict__ src, __half* __restrict__ dst,
                        int cols, int colsPad, int total)
{
    const int i = blockIdx.x * 256 + threadIdx.x;
    if (i >= total) return;
    const int r = i / colsPad, c = i % colsPad;
    dst[i] = (c < cols) ? __float2half(src[(size_t)r * cols + c]) : __half(0.f);
}

// ===========================================================================
// Fused split-K reduce + residual + LayerNorm (one block per row, 320 thr)
// ===========================================================================
template <int NP, int SET>
__global__ __launch_bounds__(320) void reduce_ln(
    const float* __restrict__ part, const float* __restrict__ bias,
    float* __restrict__ x, const float* __restrict__ lw,
    const float* __restrict__ lb, __half* __restrict__ y)
{
    const int row = blockIdx.x;
    const int tid = threadIdx.x;
    const int col = tid * 4;
    const int idx = row * DMODEL + col;
    const int TOT = S_TOK * DMODEL;

    float4 s = bias ? *(const float4*)&bias[col] : make_float4(0.f, 0.f, 0.f, 0.f);
#pragma unroll
    for (int c = 0; c < NP; c++) {
        const float4 p = *(const float4*)&part[(size_t)c * TOT + idx];
        s.x += p.x; s.y += p.y; s.z += p.z; s.w += p.w;
    }
    float4 xv;
    if (SET) {
        xv = s;
    } else {
        xv = *(const float4*)&x[idx];
        xv.x += s.x; xv.y += s.y; xv.z += s.z; xv.w += s.w;
    }
    *(float4*)&x[idx] = xv;

    float sum = xv.x + xv.y + xv.z + xv.w;
    float sq  = xv.x * xv.x + xv.y * xv.y + xv.z * xv.z + xv.w * xv.w;
#pragma unroll
    for (int o = 16; o > 0; o >>= 1) {
        sum += __shfl_xor_sync(0xffffffffu, sum, o);
        sq  += __shfl_xor_sync(0xffffffffu, sq, o);
    }
    __shared__ float ws[10], wsq[10];
    if ((tid & 31) == 0) { ws[tid >> 5] = sum; wsq[tid >> 5] = sq; }
    __syncthreads();
    __shared__ float s_mu, s_rstd;
    if (tid == 0) {
        float ts = 0.f, tsq = 0.f;
#pragma unroll
        for (int i = 0; i < 10; i++) { ts += ws[i]; tsq += wsq[i]; }
        const float mu = ts / DMODEL;
        const float var = tsq / DMODEL - mu * mu;
        s_mu = mu;
        s_rstd = rsqrtf(var + 1e-6f);
    }
    __syncthreads();
    const float mu = s_mu, rstd = s_rstd;
    const float4 w4 = *(const float4*)&lw[col];
    const float4 b4 = *(const float4*)&lb[col];
    const float o0 = (xv.x - mu) * rstd * w4.x + b4.x;
    const float o1 = (xv.y - mu) * rstd * w4.y + b4.y;
    const float o2 = (xv.z - mu) * rstd * w4.z + b4.z;
    const float o3 = (xv.w - mu) * rstd * w4.w + b4.w;
    *(uint2*)&y[idx] = make_uint2(pack_f16(o0, o1), pack_f16(o2, o3));
}

// ===========================================================================
// split-K reduce, 4 elems/thread.
// MODE 0: f32 = sum+bias; 4: f16 GELU(sum+bias); 5: f16 sum+bias;
// 6: f16 SiLU(sum+bias)
// ===========================================================================
template <int NP, int MODE>
__global__ void reduce_k(const float* __restrict__ part,
                         const float* __restrict__ bias,
                         void* __restrict__ dstv, int total, int ncols)
{
    const int i = blockIdx.x * 256 + threadIdx.x;
    const int idx = i * 4;
    if (idx >= total) return;
    float4 s = *(const float4*)&bias[idx % ncols];
#pragma unroll
    for (int c = 0; c < NP; c++) {
        const float4 p = *(const float4*)&part[(size_t)c * total + idx];
        s.x += p.x; s.y += p.y; s.z += p.z; s.w += p.w;
    }
    if (MODE == 0) {
        *(float4*)&((float*)dstv)[idx] = s;
    } else if (MODE == 4) {
        const float g0 = 0.5f * s.x * (1.f + erff(s.x * 0.7071067811865475f));
        const float g1 = 0.5f * s.y * (1.f + erff(s.y * 0.7071067811865475f));
        const float g2 = 0.5f * s.z * (1.f + erff(s.z * 0.7071067811865475f));
        const float g3 = 0.5f * s.w * (1.f + erff(s.w * 0.7071067811865475f));
        *(uint2*)&((__half*)dstv)[idx] =
            make_uint2(pack_f16(g0, g1), pack_f16(g2, g3));
    } else if (MODE == 5) {
        *(uint2*)&((__half*)dstv)[idx] =
            make_uint2(pack_f16(s.x, s.y), pack_f16(s.z, s.w));
    } else {
        const float g0 = s.x / (1.f + __expf(-1.702f * s.x));
        const float g1 = s.y / (1.f + __expf(-1.702f * s.y));
        const float g2 = s.z / (1.f + __expf(-1.702f * s.z));
        const float g3 = s.w / (1.f + __expf(-1.702f * s.w));
        *(uint2*)&((__half*)dstv)[idx] =
            make_uint2(pack_f16(g0, g1), pack_f16(g2, g3));
    }
}

// ---------------------------------------------------------------------------
// RoPE cos/sin tables
// ---------------------------------------------------------------------------
__global__ void rope_table(const float* __restrict__ rotary,
                           float* __restrict__ rcos, float* __restrict__ rsin)
{
    const int i = blockIdx.x * 256 + threadIdx.x;
    if (i >= S_TOK * 40) return;
    float c, s;
    sincosf(rotary[i], &s, &c);
    rcos[i] = c;
    rsin[i] = s;
}

// ===========================================================================
// Attention: FA2-style fp16 mma (fp32 accum), 128 thr = 4 warps, fused RoPE.
// ===========================================================================
#define AT_STRIDE 88

__device__ __forceinline__ void ldsm4(uint32_t* r, uint32_t addr) {
    asm volatile("ldmatrix.sync.aligned.m8n8.x4.shared.b16 {%0,%1,%2,%3}, [%4];"
                 : "=r"(r[0]), "=r"(r[1]), "=r"(r[2]), "=r"(r[3]) : "r"(addr));
}
__device__ __forceinline__ void ldsm4t(uint32_t* r, uint32_t addr) {
    asm volatile("ldmatrix.sync.aligned.m8n8.x4.trans.shared.b16 {%0,%1,%2,%3}, [%4];"
                 : "=r"(r[0]), "=r"(r[1]), "=r"(r[2]), "=r"(r[3]) : "r"(addr));
}

__device__ __forceinline__ void load_rope_half_h(
    const __half* __restrict__ src, const __half* __restrict__ srco,
    const float* __restrict__ tc, const float* __restrict__ ts,
    float sgn, float scale, __half* dst)
{
#pragma unroll
    for (int j = 0; j < 10; j++) {
        uint2 rv = *(const uint2*)(src + j * 4);
        uint2 rw = *(const uint2*)(srco + j * 4);
        float2 v0 = __half22float2(*(__half2*)&rv.x);
        float2 v1 = __half22float2(*(__half2*)&rv.y);
        float2 w0 = __half22float2(*(__half2*)&rw.x);
        float2 w1 = __half22float2(*(__half2*)&rw.y);
        float4 c = *(const float4*)(tc + j * 4);
        float4 s = *(const float4*)(ts + j * 4);
        float o0 = (v0.x * c.x + sgn * w0.x * s.x) * scale;
        float o1 = (v0.y * c.y + sgn * w0.y * s.y) * scale;
        float o2 = (v1.x * c.z + sgn * w1.x * s.z) * scale;
        float o3 = (v1.y * c.w + sgn * w1.y * s.w) * scale;
        *(uint2*)(dst + j * 4) = make_uint2(pack_f16(o0, o1), pack_f16(o2, o3));
    }
}

__global__ __launch_bounds__(128) void attn_f16(
    const __half* __restrict__ qkv, const int* __restrict__ seg,
    const float* __restrict__ rcos, const float* __restrict__ rsin,
    __half* __restrict__ out)
{
    __shared__ __half Qs[64 * AT_STRIDE];
    __shared__ __half Ks[64 * AT_STRIDE];
    __shared__ __half Vs[64 * AT_STRIDE];

    const int head = blockIdx.x;
    const int q0   = blockIdx.y * 64;
    const int tid  = threadIdx.x;
    const int w    = tid >> 5;
    const int lane = tid & 31;
    const int g    = lane >> 2;
    const int t    = lane & 3;

    const float scale = 0.11180339887498949f;

    uint32_t qb, kb, vb;
    asm("{ .reg .u64 u; cvta.to.shared.u64 u, %1; cvt.u32.u64 %0, u; }" : "=r"(qb) : "l"(Qs));
    asm("{ .reg .u64 u; cvta.to.shared.u64 u, %1; cvt.u32.u64 %0, u; }" : "=r"(kb) : "l"(Ks));
    asm("{ .reg .u64 u; cvta.to.shared.u64 u, %1; cvt.u32.u64 %0, u; }" : "=r"(vb) : "l"(Vs));

    const int lrow = tid >> 1;
    const int lh   = tid & 1;
    const float sgn = lh ? 1.f : -1.f;

    {
        const __half* base = qkv + (size_t)(q0 + lrow) * (3 * DMODEL) + head * HDIM;
        load_rope_half_h(base + lh * 40, base + (1 - lh) * 40,
                         rcos + (q0 + lrow) * 40, rsin + (q0 + lrow) * 40,
                         sgn, scale, Qs + lrow * AT_STRIDE + lh * 40);
    }

    float m[2] = {-1e30f, -1e30f};
    float l[2] = {0.f, 0.f};
    float oacc[10][4];
#pragma unroll
    for (int j = 0; j < 10; j++)
#pragma unroll
        for (int i = 0; i < 4; i++) oacc[j][i] = 0.f;

    const int myseg = seg[q0];

    const uint32_t lrow16 = (uint32_t)(lane & 15);
    const uint32_t lhi16  = (uint32_t)(lane >> 4) * 16;
    const uint32_t q_addr0 = qb + (w * 16 + lrow16) * (AT_STRIDE * 2) + lhi16;

    __syncthreads();

    for (int c0 = 0; c0 < S_TOK; c0 += 64) {
        if (seg[c0] != myseg) continue;

        {
            const __half* baseK = qkv + (size_t)(c0 + lrow) * (3 * DMODEL) + DMODEL + head * HDIM;
            load_rope_half_h(baseK + lh * 40, baseK + (1 - lh) * 40,
                             rcos + (c0 + lrow) * 40, rsin + (c0 + lrow) * 40,
                             sgn, 1.f, Ks + lrow * AT_STRIDE + lh * 40);
            const __half* srcV = baseK + DMODEL + lh * 40;
            __half* dV = Vs + lrow * AT_STRIDE + lh * 40;
#pragma unroll
            for (int j = 0; j < 10; j++)
                *(uint2*)(dV + j * 4) = *(const uint2*)(srcV + j * 4);
        }
        __syncthreads();

        float sacc[8][4];
#pragma unroll
        for (int j = 0; j < 8; j++)
#pragma unroll
            for (int i = 0; i < 4; i++) sacc[j][i] = 0.f;

#pragma unroll
        for (int ks = 0; ks < 5; ks++) {
            uint32_t aq[4];
            ldsm4(aq, q_addr0 + ks * 32);
#pragma unroll
            for (int nb = 0; nb < 4; nb++) {
                uint32_t kr[4];
                ldsm4(kr, kb + (nb * 16 + lrow16) * (AT_STRIDE * 2) + lhi16 + ks * 32);
                mma_f16(sacc[2 * nb],     aq[0], aq[1], aq[2], aq[3], kr[0], kr[2]);
                mma_f16(sacc[2 * nb + 1], aq[0], aq[1], aq[2], aq[3], kr[1], kr[3]);
            }
        }

        float cs[2];
#pragma unroll
        for (int i = 0; i < 2; i++) {
            float cm = -1e30f;
#pragma unroll
            for (int j = 0; j < 8; j++) {
                cm = fmaxf(cm, sacc[j][2 * i]);
                cm = fmaxf(cm, sacc[j][2 * i + 1]);
            }
            cm = fmaxf(cm, __shfl_xor_sync(0xffffffffu, cm, 1));
            cm = fmaxf(cm, __shfl_xor_sync(0xffffffffu, cm, 2));
            const float nm = fmaxf(m[i], cm);
            cs[i] = __expf(m[i] - nm);
            m[i] = nm;
            float ps = 0.f;
#pragma unroll
            for (int j = 0; j < 8; j++) {
                float p0 = __expf(sacc[j][2 * i] - nm);
                float p1 = __expf(sacc[j][2 * i + 1] - nm);
                sacc[j][2 * i] = p0; sacc[j][2 * i + 1] = p1;
                ps += p0 + p1;
            }
            ps += __shfl_xor_sync(0xffffffffu, ps, 1);
            ps += __shfl_xor_sync(0xffffffffu, ps, 2);
            l[i] = l[i] * cs[i] + ps;
        }
#pragma unroll
        for (int j = 0; j < 10; j++) {
            oacc[j][0] *= cs[0]; oacc[j][1] *= cs[0];
            oacc[j][2] *= cs[1]; oacc[j][3] *= cs[1];
        }

#pragma unroll
        for (int ks = 0; ks < 4; ks++) {
            uint32_t pp[4];
            pp[0] = pack_f16(sacc[2 * ks][0],     sacc[2 * ks][1]);
            pp[1] = pack_f16(sacc[2 * ks][2],     sacc[2 * ks][3]);
            pp[2] = pack_f16(sacc[2 * ks + 1][0], sacc[2 * ks + 1][1]);
            pp[3] = pack_f16(sacc[2 * ks + 1][2], sacc[2 * ks + 1][3]);
#pragma unroll
            for (int db = 0; db < 5; db++) {
                uint32_t vr[4];
                ldsm4t(vr, vb + (ks * 16 + lrow16) * (AT_STRIDE * 2) + db * 32 + lhi16);
                mma_f16(oacc[2 * db],     pp[0], pp[1], pp[2], pp[3], vr[0], vr[1]);
                mma_f16(oacc[2 * db + 1], pp[0], pp[1], pp[2], pp[3], vr[2], vr[3]);
            }
        }
        __syncthreads();
    }

    const float inv0 = 1.f / l[0];
    const float inv1 = 1.f / l[1];
    const int r0 = q0 + w * 16 + g;
#pragma unroll
    for (int j = 0; j < 10; j++) {
        const int d = head * HDIM + j * 8 + t * 2;
        *(uint32_t*)&out[(size_t)r0 * DMODEL + d] =
            pack_f16(oacc[j][0] * inv0, oacc[j][1] * inv0);
        *(uint32_t*)&out[(size_t)(r0 + 8) * DMODEL + d] =
            pack_f16(oacc[j][2] * inv1, oacc[j][3] * inv1);
    }
}

// ---------------------------------------------------------------------------
// Host side
// ---------------------------------------------------------------------------
static inline void run_splitk(int parts, const __half* A, int ld,
                              const __half* B, float* part_buf,
                              int M, int N, int Kfull)
{
    dim3 grid(N / 256, (M + 127) / 128, parts);
    gemm_h<4><<<grid, 256, GEMM_SMEM_BYTES>>>(A, ld, B, ld, nullptr,
                                              part_buf, M, N, Kfull / parts);
}

extern "C" void kernel_launch(void* const* d_in, const int* in_sizes, int n_in,
                              void* d_out, int out_size)
{
    const float* pixels  = (const float*)d_in[0];
    const float* rotary  = (const float*)d_in[1];
    const int*   seg_ids = (const int*)d_in[2];
    const float* proj_w  = (const float*)d_in[3];
    const float* ln1_w   = (const float*)d_in[4];
    const float* ln1_b   = (const float*)d_in[5];
    const float* qkv_w   = (const float*)d_in[6];
    const float* qkv_b   = (const float*)d_in[7];
    const float* po_w    = (const float*)d_in[8];
    const float* po_b    = (const float*)d_in[9];
    const float* ln2_w   = (const float*)d_in[10];
    const float* ln2_b   = (const float*)d_in[11];
    const float* fc1_w   = (const float*)d_in[12];
    const float* fc1_b   = (const float*)d_in[13];
    const float* fc2_w   = (const float*)d_in[14];
    const float* fc2_b   = (const float*)d_in[15];
    const float* mln_w   = (const float*)d_in[16];
    const float* mln_b   = (const float*)d_in[17];
    const float* m1_w    = (const float*)d_in[18];
    const float* m1_b    = (const float*)d_in[19];
    const float* m2_w    = (const float*)d_in[20];
    const float* m2_b    = (const float*)d_in[21];
    float* out = (float*)d_out;

    float *x, *part, *rcos, *rsin;
    __half *pixh, *projwh, *qkvwh, *powh, *fc1wh, *fc2wh, *m1wh, *m2wh;
    __half *lnh, *qkvh, *atth, *bigh;
    cudaGetSymbolAddress((void**)&x,      g_x);
    cudaGetSymbolAddress((void**)&part,   g_part);
    cudaGetSymbolAddress((void**)&rcos,   g_rcos);
    cudaGetSymbolAddress((void**)&rsin,   g_rsin);
    cudaGetSymbolAddress((void**)&pixh,   g_pix_h);
    cudaGetSymbolAddress((void**)&projwh, g_projw_h);
    cudaGetSymbolAddress((void**)&qkvwh,  g_qkvw_h);
    cudaGetSymbolAddress((void**)&powh,   g_pow_h);
    cudaGetSymbolAddress((void**)&fc1wh,  g_fc1w_h);
    cudaGetSymbolAddress((void**)&fc2wh,  g_fc2w_h);
    cudaGetSymbolAddress((void**)&m1wh,   g_m1w_h);
    cudaGetSymbolAddress((void**)&m2wh,   g_m2w_h);
    cudaGetSymbolAddress((void**)&lnh,    g_ln_h);
    cudaGetSymbolAddress((void**)&qkvh,   g_qkv_h);
    cudaGetSymbolAddress((void**)&atth,   g_att_h);
    cudaGetSymbolAddress((void**)&bigh,   g_big_h);

    cudaFuncSetAttribute(gemm_h<4>, cudaFuncAttributeMaxDynamicSharedMemorySize, GEMM_SMEM_BYTES);

    // weight conversions
    {
        const long long n_qkv = (long long)DEPTH * 3 * DMODEL * DMODEL / 8;
        const long long n_po  = (long long)DEPTH * DMODEL * DMODEL / 8;
        const long long n_fc1 = (long long)DEPTH * 4 * DMODEL * DMODEL / 8;
        const long long n_fc2 = (long long)DEPTH * DMODEL * 4 * DMODEL / 8;
        const long long n_m1  = (long long)4 * DMODEL * 4 * DMODEL / 8;
        const long long n_m2  = (long long)1536 * 4 * DMODEL / 8;
        const long long e0 = n_qkv;
        const long long e1 = e0 + n_po;
        const long long e2 = e1 + n_fc1;
        const long long e3 = e2 + n_fc2;
        const long long e4 = e3 + n_m1;
        const long long e5 = e4 + n_m2;
        cvt_merged<<<(unsigned)((e5 + 255) / 256), 256>>>(
            qkv_w, qkvwh, e0, po_w, powh, e1, fc1_w, fc1wh, e2,
            fc2_w, fc2wh, e3, m1_w, m1wh, e4, m2_w, m2wh, e5);

        const int tp = S_TOK * KPAD;
        cvt_pad<<<(tp + 255) / 256, 256>>>(pixels, pixh, 1176, KPAD, tp);
        const int tw = DMODEL * KPAD;
        cvt_pad<<<(tw + 255) / 256, 256>>>(proj_w, projwh, 1176, KPAD, tw);
    }
    rope_table<<<(S_TOK * 40 + 255) / 256, 256>>>(rotary, rcos, rsin);

    // proj: split-K x2 -> fused reduce (x = sum) + LN1(layer0) -> lnh
    run_splitk(2, pixh, KPAD, projwh, part, S_TOK, DMODEL, KPAD);
    reduce_ln<2, 1><<<S_TOK, 320>>>(part, nullptr, x, ln1_w, ln1_b, lnh);

    for (int l = 0; l < DEPTH; l++) {
        // qkv: split-K x2 -> reduce (+bias) -> fp16 qkvh
        run_splitk(2, lnh, DMODEL, qkvwh + (size_t)l * 3 * DMODEL * DMODEL,
                   part, S_TOK, 3 * DMODEL, DMODEL);
        reduce_k<2, 5><<<(S_TOK * 3 * DMODEL / 4 + 255) / 256, 256>>>(
            part, qkv_b + (size_t)l * 3 * DMODEL, qkvh,
            S_TOK * 3 * DMODEL, 3 * DMODEL);
        {
            dim3 grid(NHEAD, S_TOK / 64);
            attn_f16<<<grid, 128>>>(qkvh, seg_ids, rcos, rsin, atth);
        }
        // po: split-K x8 -> fused (x += sum+bias) + LN2 -> lnh
        run_splitk(8, atth, DMODEL, powh + (size_t)l * DMODEL * DMODEL, part,
                   S_TOK, DMODEL, DMODEL);
        reduce_ln<8, 0><<<S_TOK, 320>>>(part, po_b + (size_t)l * DMODEL, x,
                                        ln2_w + l * DMODEL, ln2_b + l * DMODEL, lnh);

        // fc1: split-K x2 -> reduce (+bias, SiLU) -> fp16 bigh
        run_splitk(2, lnh, DMODEL, fc1wh + (size_t)l * 4 * DMODEL * DMODEL,
                   part, S_TOK, 4 * DMODEL, DMODEL);
        reduce_k<2, 6><<<(S_TOK * 4 * DMODEL / 4 + 255) / 256, 256>>>(
            part, fc1_b + (size_t)l * 4 * DMODEL, bigh,
            S_TOK * 4 * DMODEL, 4 * DMODEL);
        // fc2: split-K x8 -> fused (x += sum+bias) + next LN
        run_splitk(8, bigh, 4 * DMODEL,
                   fc2wh + (size_t)l * DMODEL * 4 * DMODEL, part,
                   S_TOK, DMODEL, 4 * DMODEL);
        const float* nw = (l + 1 < DEPTH) ? ln1_w + (l + 1) * DMODEL : mln_w;
        const float* nb = (l + 1 < DEPTH) ? ln1_b + (l + 1) * DMODEL : mln_b;
        reduce_ln<8, 0><<<S_TOK, 320>>>(part, fc2_b + (size_t)l * DMODEL, x,
                                        nw, nb, lnh);
    }

    // m1: split-K x4, GELU->fp16 in reduce -> bigh
    run_splitk(4, lnh, 4 * DMODEL, m1wh, part, S_TOK / 4, 4 * DMODEL, 4 * DMODEL);
    reduce_k<4, 4><<<(320 * 4 * DMODEL / 4 + 255) / 256, 256>>>(
        part, m1_b, bigh, 320 * 4 * DMODEL, 4 * DMODEL);
    // m2: split-K x8 -> reduce -> out (fp32)
    run_splitk(8, bigh, 4 * DMODEL, m2wh, part, 320, 1536, 4 * DMODEL);
    reduce_k<8, 0><<<(320 * 1536 / 4 + 255) / 256, 256>>>(
        part, m2_b, out, 320 * 1536, 1536);
}